// round 9
// baseline (speedup 1.0000x reference)
#include <cuda_runtime.h>
#include <cuda_bf16.h>
#include <cuda_fp8.h>
#include <math.h>
#include <stdint.h>

// Problem constants (fixed by the reference)
#define BB 2
#define SS 2048
#define DD 512
#define VV 32000
#define HH 4
#define DH 128
#define WW 3
#define NN (BB*SS)   // 4096
#define KP 1536      // GAT split-bf16 K' = 3*512
#define NCH_GAT 24   // KP / 64
#define NCH_LM  8    // 512 / 64

// fp8 correction scales (powers of two)
#define SC_HI 64.0f                    // 2^6
#define SC_LO 32768.0f                 // 2^15
#define SC_OUT 4.76837158203125e-07f   // 2^-21

// Scratch (device globals; no allocation allowed)
__device__ float g_x   [NN*DD];
__device__ float g_x2  [NN*DD];
__device__ float g_wx  [NN*DD];
__device__ float g_agg [NN*DD];
__device__ float g_ssrc[NN*HH];
__device__ float g_sdst[NN*HH];
__device__ __nv_bfloat16 g_Ap[(size_t)NN*KP];     // GAT A split [Ah|Ah|Al]
__device__ __nv_bfloat16 g_Wp[(size_t)DD*KP];     // GAT W split [Bh|Bl|Bh]
__device__ __nv_bfloat16 g_Ah[(size_t)NN*DD];     // LM head A hi (bf16)
__device__ uint8_t       g_Ac[(size_t)NN*2*DD];   // LM head A corr fp8 [Ah8|Al8]
__device__ __nv_bfloat16 g_Bh[(size_t)VV*DD];     // LM head B hi (bf16)
__device__ uint8_t       g_Bc[(size_t)VV*2*DD];   // LM head B corr fp8 [Bl8|Bh8]

// ---------------------------------------------------------------------------
// PTX helpers (sm_80/89-era: cp.async, ldmatrix, mma.sync — valid at compute_103.
// tcgen05 is NOT available at the harness's virtual PTX target.)
// ---------------------------------------------------------------------------
__device__ __forceinline__ uint32_t smem_u32(const void* p) {
    uint32_t a;
    asm("{ .reg .u64 t; cvta.to.shared.u64 t, %1; cvt.u32.u64 %0, t; }"
        : "=r"(a) : "l"(p));
    return a;
}
__device__ __forceinline__ void cp_async16(uint32_t dst, const void* src) {
    asm volatile("cp.async.cg.shared.global [%0], [%1], 16;\n" :: "r"(dst), "l"(src));
}
#define CP_COMMIT() asm volatile("cp.async.commit_group;\n" ::: "memory")
template<int Nw> __device__ __forceinline__ void cp_wait() {
    asm volatile("cp.async.wait_group %0;\n" :: "n"(Nw) : "memory");
}
__device__ __forceinline__ void ldmatrix_x4(uint32_t& r0, uint32_t& r1,
                                            uint32_t& r2, uint32_t& r3, uint32_t addr) {
    asm volatile("ldmatrix.sync.aligned.m8n8.x4.shared.b16 {%0,%1,%2,%3}, [%4];\n"
                 : "=r"(r0), "=r"(r1), "=r"(r2), "=r"(r3) : "r"(addr));
}
__device__ __forceinline__ void mma_bf16(float* c,
                                         uint32_t a0, uint32_t a1, uint32_t a2, uint32_t a3,
                                         uint32_t b0, uint32_t b1) {
    asm volatile(
        "mma.sync.aligned.m16n8k16.row.col.f32.bf16.bf16.f32 "
        "{%0,%1,%2,%3}, {%4,%5,%6,%7}, {%8,%9}, {%0,%1,%2,%3};\n"
        : "+f"(c[0]), "+f"(c[1]), "+f"(c[2]), "+f"(c[3])
        : "r"(a0), "r"(a1), "r"(a2), "r"(a3), "r"(b0), "r"(b1));
}
__device__ __forceinline__ void mma_fp8(float* c,
                                        uint32_t a0, uint32_t a1, uint32_t a2, uint32_t a3,
                                        uint32_t b0, uint32_t b1) {
    asm volatile(
        "mma.sync.aligned.m16n8k32.row.col.f32.e4m3.e4m3.f32 "
        "{%0,%1,%2,%3}, {%4,%5,%6,%7}, {%8,%9}, {%0,%1,%2,%3};\n"
        : "+f"(c[0]), "+f"(c[1]), "+f"(c[2]), "+f"(c[3])
        : "r"(a0), "r"(a1), "r"(a2), "r"(a3), "r"(b0), "r"(b1));
}
__device__ __forceinline__ uint8_t f2e4m3(float x) {
    return (uint8_t)__nv_cvt_float_to_fp8(x, __NV_SATFINITE, __NV_E4M3);
}

// ---------------------------------------------------------------------------
// Embedding gather
// ---------------------------------------------------------------------------
__global__ void gather_k(const int* __restrict__ ids,
                         const float* __restrict__ emb,
                         float* __restrict__ x)
{
    int idx = blockIdx.x * blockDim.x + threadIdx.x;
    int n  = idx / (DD/4);
    int d4 = idx % (DD/4);
    const float4* srcp = (const float4*)(emb + (size_t)ids[n]*DD) + d4;
    float4* dstp = (float4*)(x + (size_t)n*DD) + d4;
    *dstp = *srcp;
}

// ---------------------------------------------------------------------------
// GAT conversions: fp32 -> K-concatenated bf16 splits
// ---------------------------------------------------------------------------
__global__ void conv_A_k(const float* __restrict__ src, __nv_bfloat16* __restrict__ dst)
{
    size_t i = (size_t)blockIdx.x * blockDim.x + threadIdx.x;
    size_t r = i / (DD/4);
    int c = (int)(i % (DD/4)) * 4;
    float4 v = *(const float4*)(src + r*DD + c);
    float f[4] = {v.x, v.y, v.z, v.w};
    __nv_bfloat16* base = dst + r*KP + c;
    #pragma unroll
    for (int j = 0; j < 4; j++) {
        __nv_bfloat16 h = __float2bfloat16(f[j]);
        __nv_bfloat16 l = __float2bfloat16(f[j] - __bfloat162float(h));
        base[j]        = h;
        base[512 + j]  = h;
        base[1024 + j] = l;
    }
}
__global__ void conv_B_k(const float* __restrict__ src, __nv_bfloat16* __restrict__ dst)
{
    size_t i = (size_t)blockIdx.x * blockDim.x + threadIdx.x;
    size_t r = i / (DD/4);
    int c = (int)(i % (DD/4)) * 4;
    float4 v = *(const float4*)(src + r*DD + c);
    float f[4] = {v.x, v.y, v.z, v.w};
    __nv_bfloat16* base = dst + r*KP + c;
    #pragma unroll
    for (int j = 0; j < 4; j++) {
        __nv_bfloat16 h = __float2bfloat16(f[j]);
        __nv_bfloat16 l = __float2bfloat16(f[j] - __bfloat162float(h));
        base[j]        = h;
        base[512 + j]  = l;
        base[1024 + j] = h;
    }
}

// ---------------------------------------------------------------------------
// LM-head conversions: fp32 -> bf16 hi + fp8 corr blocks (proven in Round 4)
// A: Ah bf16; Acorr = [fp8(Ah*2^6) | fp8(Al*2^15)]
// B: Bh bf16; Bcorr = [fp8(Bl*2^15) | fp8(Bh*2^6)]
// corr product accumulates AhBl + AlBh at scale 2^21.
// ---------------------------------------------------------------------------
__global__ void conv_lmA_k(const float* __restrict__ src,
                           __nv_bfloat16* __restrict__ ah, uint8_t* __restrict__ ac)
{
    size_t i = (size_t)blockIdx.x * blockDim.x + threadIdx.x;
    size_t r = i / (DD/4);
    int c = (int)(i % (DD/4)) * 4;
    float4 v = *(const float4*)(src + r*DD + c);
    float f[4] = {v.x, v.y, v.z, v.w};
    #pragma unroll
    for (int j = 0; j < 4; j++) {
        __nv_bfloat16 h = __float2bfloat16(f[j]);
        float hf = __bfloat162float(h);
        float l  = f[j] - hf;
        ah[r*DD + c + j]         = h;
        ac[r*2*DD + c + j]       = f2e4m3(hf * SC_HI);
        ac[r*2*DD + 512 + c + j] = f2e4m3(l  * SC_LO);
    }
}
__global__ void conv_lmB_k(const float* __restrict__ src,
                           __nv_bfloat16* __restrict__ bh, uint8_t* __restrict__ bc)
{
    size_t i = (size_t)blockIdx.x * blockDim.x + threadIdx.x;
    size_t r = i / (DD/4);
    int c = (int)(i % (DD/4)) * 4;
    float4 v = *(const float4*)(src + r*DD + c);
    float f[4] = {v.x, v.y, v.z, v.w};
    #pragma unroll
    for (int j = 0; j < 4; j++) {
        __nv_bfloat16 h = __float2bfloat16(f[j]);
        float hf = __bfloat162float(h);
        float l  = f[j] - hf;
        bh[r*DD + c + j]         = h;
        bc[r*2*DD + c + j]       = f2e4m3(l  * SC_LO);
        bc[r*2*DD + 512 + c + j] = f2e4m3(hf * SC_HI);
    }
}

// ---------------------------------------------------------------------------
// Per-node attention scores
// ---------------------------------------------------------------------------
__global__ void scores_k(const float* __restrict__ wx,
                         const float* __restrict__ a,
                         float* __restrict__ ssrc,
                         float* __restrict__ sdst)
{
    int w    = (blockIdx.x * blockDim.x + threadIdx.x) >> 5;
    int lane = threadIdx.x & 31;
    if (w >= NN*HH) return;
    int n = w / HH, h = w % HH;
    const float* row = wx + (size_t)n*DD + h*DH;
    const float* au  = a + (size_t)h*2*DH;
    const float* av  = au + DH;

    int d = lane * 4;
    float4 x = *(const float4*)(row + d);
    float4 u = *(const float4*)(au  + d);
    float4 v = *(const float4*)(av  + d);
    float s1 = x.x*u.x + x.y*u.y + x.z*u.z + x.w*u.w;
    float s2 = x.x*v.x + x.y*v.y + x.z*v.z + x.w*v.w;
    #pragma unroll
    for (int o = 16; o; o >>= 1) {
        s1 += __shfl_xor_sync(0xffffffffu, s1, o);
        s2 += __shfl_xor_sync(0xffffffffu, s2, o);
    }
    if (lane == 0) { ssrc[w] = s1; sdst[w] = s2; }
}

// ---------------------------------------------------------------------------
// Windowed GAT aggregation
// ---------------------------------------------------------------------------
__global__ void attn_k(const float* __restrict__ wx,
                       const float* __restrict__ ssrc,
                       const float* __restrict__ sdst,
                       float* __restrict__ agg)
{
    int n    = blockIdx.x;
    int h    = threadIdx.x >> 5;
    int lane = threadIdx.x & 31;
    int i    = n % SS;

    float sd = sdst[(size_t)n*HH + h];

    float e[2*WW];
    int   jn[2*WW];
    int cnt = 0;
    #pragma unroll
    for (int off = -WW; off <= WW; off++) {
        if (off == 0) continue;
        int ji = i + off;
        if (ji < 0 || ji >= SS) continue;
        int j = n + off;
        float v = ssrc[(size_t)j*HH + h] + sd;
        v = v >= 0.f ? v : 0.2f * v;
        e[cnt] = v; jn[cnt] = j; cnt++;
    }
    float m = -1e30f;
    for (int c = 0; c < cnt; c++) m = fmaxf(m, e[c]);
    float den = 0.f;
    for (int c = 0; c < cnt; c++) { e[c] = expf(e[c] - m); den += e[c]; }
    float inv = 1.f / (den + 1e-16f);

    int d = lane * 4;
    float4 accv = make_float4(0.f, 0.f, 0.f, 0.f);
    for (int c = 0; c < cnt; c++) {
        const float4 xv = *(const float4*)(wx + (size_t)jn[c]*DD + h*DH + d);
        float al = e[c] * inv;
        accv.x = fmaf(al, xv.x, accv.x);
        accv.y = fmaf(al, xv.y, accv.y);
        accv.z = fmaf(al, xv.z, accv.z);
        accv.w = fmaf(al, xv.w, accv.w);
    }
    *(float4*)(agg + (size_t)n*DD + h*DH + d) = accv;
}

// ---------------------------------------------------------------------------
// GAT mma GEMM (split-bf16 K'=1536): unchanged (passing, small share of time)
// ---------------------------------------------------------------------------
#define G_STAGES 3
#define G_STAGE_BYTES 32768
#define G_SMEM (G_STAGES*G_STAGE_BYTES)

__device__ __forceinline__ void load_stage_gat(
    const __nv_bfloat16* __restrict__ Ap, const __nv_bfloat16* __restrict__ Bp,
    int row0, int col0, int k0, uint32_t stage_base, int tid)
{
    #pragma unroll
    for (int it = 0; it < 8; it++) {
        int g = tid + it*256;
        bool isA = (g < 1024);
        int gg  = isA ? g : (g - 1024);
        int row = gg >> 3;
        int gran = gg & 7;
        const __nv_bfloat16* src = isA
            ? (Ap + (size_t)(row0 + row)*KP + k0 + gran*8)
            : (Bp + (size_t)(col0 + row)*KP + k0 + gran*8);
        uint32_t dst = stage_base + (isA ? 0u : 16384u)
                     + (uint32_t)row*128u + (uint32_t)((gran ^ (row & 7)) << 4);
        cp_async16(dst, src);
    }
}

template<int EPI>
__global__ void __launch_bounds__(256, 2)
gat_mma_k(const __nv_bfloat16* __restrict__ Ap,
          const __nv_bfloat16* __restrict__ Bp,
          const float* __restrict__ bias,
          float* __restrict__ C)
{
    extern __shared__ char smem[];
    const uint32_t sb = smem_u32(smem);
    const int tid  = threadIdx.x;
    const int wid  = tid >> 5;
    const int lane = tid & 31;
    const int row0 = blockIdx.x * 128;
    const int col0 = blockIdx.y * 128;

    const int warp_m = wid & 3;
    const int warp_n = wid >> 2;

    float acc[2][8][4];
    #pragma unroll
    for (int i = 0; i < 2; i++)
        #pragma unroll
        for (int j = 0; j < 8; j++)
            #pragma unroll
            for (int q = 0; q < 4; q++) acc[i][j][q] = 0.f;

    load_stage_gat(Ap, Bp, row0, col0, 0,  sb,                 tid); CP_COMMIT();
    load_stage_gat(Ap, Bp, row0, col0, 64, sb + G_STAGE_BYTES, tid); CP_COMMIT();

    const int a_row  = warp_m*32 + (lane & 15);
    const int a_gsel = lane >> 4;
    const int b_row  = warp_n*64 + ((lane >> 4) << 3) + (lane & 7);
    const int b_gsel = (lane >> 3) & 1;

    for (int c = 0; c < NCH_GAT; c++) {
        cp_wait<G_STAGES-2>();
        __syncthreads();

        if (c + 2 < NCH_GAT)
            load_stage_gat(Ap, Bp, row0, col0, (c+2)*64,
                           sb + ((c+2)%G_STAGES)*G_STAGE_BYTES, tid);
        CP_COMMIT();

        const uint32_t sA = sb + (c%G_STAGES)*G_STAGE_BYTES;
        const uint32_t sB = sA + 16384u;

        #pragma unroll
        for (int s = 0; s < 4; s++) {
            uint32_t a[2][4];
            #pragma unroll
            for (int mi = 0; mi < 2; mi++) {
                int r = a_row + mi*16;
                int gran = 2*s + a_gsel;
                uint32_t addr = sA + (uint32_t)r*128u + (uint32_t)((gran ^ (r & 7)) << 4);
                ldmatrix_x4(a[mi][0], a[mi][1], a[mi][2], a[mi][3], addr);
            }
            uint32_t b[8][2];
            #pragma unroll
            for (int ng = 0; ng < 4; ng++) {
                int r = b_row + ng*16;
                int gran = 2*s + b_gsel;
                uint32_t addr = sB + (uint32_t)r*128u + (uint32_t)((gran ^ (r & 7)) << 4);
                uint32_t r0, r1, r2, r3;
                ldmatrix_x4(r0, r1, r2, r3, addr);
                b[ng*2+0][0] = r0; b[ng*2+0][1] = r1;
                b[ng*2+1][0] = r2; b[ng*2+1][1] = r3;
            }
            #pragma unroll
            for (int mi = 0; mi < 2; mi++)
                #pragma unroll
                for (int nj = 0; nj < 8; nj++)
                    mma_bf16(acc[mi][nj], a[mi][0], a[mi][1], a[mi][2], a[mi][3],
                             b[nj][0], b[nj][1]);
        }
    }

    const int trow = lane >> 2;
    const int tcol = (lane & 3) * 2;
    #pragma unroll
    for (int mi = 0; mi < 2; mi++) {
        const int mbase = row0 + warp_m*32 + mi*16 + trow;
        #pragma unroll
        for (int nj = 0; nj < 8; nj++) {
            const int col = col0 + warp_n*64 + nj*8 + tcol;
            float vv[4] = {acc[mi][nj][0], acc[mi][nj][1], acc[mi][nj][2], acc[mi][nj][3]};
            if (EPI == 1) {
                const float b0 = __ldg(bias + col);
                const float b1 = __ldg(bias + col + 1);
                vv[0] += b0; vv[1] += b1; vv[2] += b0; vv[3] += b1;
                #pragma unroll
                for (int q = 0; q < 4; q++)
                    vv[q] = vv[q] > 0.f ? vv[q] : (expf(vv[q]) - 1.f);
            }
            *(float2*)(C + (size_t)mbase*DD + col)     = make_float2(vv[0], vv[1]);
            *(float2*)(C + (size_t)(mbase+8)*DD + col) = make_float2(vv[2], vv[3]);
        }
    }
}

// ---------------------------------------------------------------------------
// LM head v7: C = Ah@Bh^T (bf16 K=512) + 2^-21 * Ac@Bc^T (fp8 K'=1024) + bias.
// 33% fewer MMA instructions than split-3 (the mma.sync rate ceiling is the wall).
// CTA 128x128, 8 warps (2m x 4n), warp tile 64x32, dual accumulators.
// BK=64/chunk (fp8 corr advances 128 fp8/chunk), 3-stage cp.async, 192KB smem.
// ---------------------------------------------------------------------------
#define L_STAGES 3
#define L_STAGE_BYTES 65536   // Ah 16K + Bh 16K + Ac 16K + Bc 16K
#define L_SMEM (L_STAGES*L_STAGE_BYTES)
#define L_OFF_BH 16384u
#define L_OFF_AC 32768u
#define L_OFF_BC 49152u

__device__ __forceinline__ void load_stage_lm(
    const __nv_bfloat16* __restrict__ Ah, const __nv_bfloat16* __restrict__ Bh,
    const uint8_t* __restrict__ Ac, const uint8_t* __restrict__ Bc,
    int row0, int col0, int k0, uint32_t stage_base, int tid)
{
    #pragma unroll
    for (int it = 0; it < 16; it++) {
        int g = tid + it*256;          // 0..4095 granules of 16B
        int sel = g >> 10;             // 0:Ah 1:Bh 2:Ac 3:Bc (1024 granules each)
        int gg  = g & 1023;
        int row = gg >> 3;             // 0..127
        int gran = gg & 7;
        const void* src;
        if (sel == 0)      src = Ah + (size_t)(row0 + row)*DD + k0 + gran*8;
        else if (sel == 1) src = Bh + (size_t)(col0 + row)*DD + k0 + gran*8;
        else if (sel == 2) src = Ac + (size_t)(row0 + row)*2*DD + 2*k0 + gran*16;
        else               src = Bc + (size_t)(col0 + row)*2*DD + 2*k0 + gran*16;
        uint32_t dst = stage_base + (uint32_t)sel*16384u
                     + (uint32_t)row*128u + (uint32_t)((gran ^ (row & 7)) << 4);
        cp_async16(dst, src);
    }
}

__global__ void __launch_bounds__(256, 1)
lmhead_k(const __nv_bfloat16* __restrict__ Ah,
         const __nv_bfloat16* __restrict__ Bh,
         const uint8_t* __restrict__ Ac,
         const uint8_t* __restrict__ Bc,
         const float* __restrict__ bias,
         float* __restrict__ C)
{
    extern __shared__ char smem[];
    const uint32_t sb = smem_u32(smem);
    const int tid  = threadIdx.x;
    const int wid  = tid >> 5;
    const int lane = tid & 31;
    const int row0 = blockIdx.x * 128;
    const int col0 = blockIdx.y * 128;

    const int warp_m = wid & 1;      // 2(m) x 4(n); warp tile 64x32
    const int warp_n = wid >> 1;

    float hi[4][4][4], co[4][4][4];
    #pragma unroll
    for (int i = 0; i < 4; i++)
        #pragma unroll
        for (int j = 0; j < 4; j++)
            #pragma unroll
            for (int q = 0; q < 4; q++) { hi[i][j][q] = 0.f; co[i][j][q] = 0.f; }

    load_stage_lm(Ah, Bh, Ac, Bc, row0, col0, 0,  sb,                 tid); CP_COMMIT();
    load_stage_lm(Ah, Bh, Ac, Bc, row0, col0, 64, sb + L_STAGE_BYTES, tid); CP_COMMIT();

    const int a_row  = warp_m*64 + (lane & 15);
    const int a_gsel = lane >> 4;
    const int b_row  = warp_n*32 + ((lane >> 4) << 3) + (lane & 7);
    const int b_gsel = (lane >> 3) & 1;

    for (int c = 0; c < NCH_LM; c++) {
        cp_wait<L_STAGES-2>();
        __syncthreads();

        if (c + 2 < NCH_LM)
            load_stage_lm(Ah, Bh, Ac, Bc, row0, col0, (c+2)*64,
                          sb + ((c+2)%L_STAGES)*L_STAGE_BYTES, tid);
        CP_COMMIT();

        const uint32_t st  = sb + (c%L_STAGES)*L_STAGE_BYTES;
        const uint32_t sAh = st;
        const uint32_t sBh = st + L_OFF_BH;
        const uint32_t sAc = st + L_OFF_AC;
        const uint32_t sBc = st + L_OFF_BC;

        #pragma unroll
        for (int s = 0; s < 4; s++) {
            // ---- bf16 hi: k16 step ----
            {
                uint32_t a[4][4];
                #pragma unroll
                for (int mi = 0; mi < 4; mi++) {
                    int r = a_row + mi*16;
                    int g = 2*s + a_gsel;
                    uint32_t addr = sAh + (uint32_t)r*128u + (uint32_t)((g ^ (r & 7)) << 4);
                    ldmatrix_x4(a[mi][0], a[mi][1], a[mi][2], a[mi][3], addr);
                }
                uint32_t b[4][2];
                #pragma unroll
                for (int ng = 0; ng < 2; ng++) {
                    int r = b_row + ng*16;
                    int g = 2*s + b_gsel;
                    uint32_t addr = sBh + (uint32_t)r*128u + (uint32_t)((g ^ (r & 7)) << 4);
                    uint32_t r0, r1, r2, r3;
                    ldmatrix_x4(r0, r1, r2, r3, addr);
                    b[ng*2+0][0] = r0; b[ng*2+0][1] = r1;
                    b[ng*2+1][0] = r2; b[ng*2+1][1] = r3;
                }
                #pragma unroll
                for (int mi = 0; mi < 4; mi++)
                    #pragma unroll
                    for (int nj = 0; nj < 4; nj++)
                        mma_bf16(hi[mi][nj], a[mi][0], a[mi][1], a[mi][2], a[mi][3],
                                 b[nj][0], b[nj][1]);
            }
            // ---- fp8 corr: k32 step over the 128-fp8 chunk ----
            {
                uint32_t a[4][4];
                #pragma unroll
                for (int mi = 0; mi < 4; mi++) {
                    int r = a_row + mi*16;
                    int g = 2*s + a_gsel;
                    uint32_t addr = sAc + (uint32_t)r*128u + (uint32_t)((g ^ (r & 7)) << 4);
                    ldmatrix_x4(a[mi][0], a[mi][1], a[mi][2], a[mi][3], addr);
                }
                uint32_t b[4][2];
                #pragma unroll
                for (int ng = 0; ng < 2; ng++) {
                    int r = b_row + ng*16;
                    int g = 2*s + b_gsel;
                    uint32_t addr = sBc + (uint32_t)r*128u + (uint32_t)((g ^ (r & 7)) << 4);
                    uint32_t r0, r1, r2, r3;
                    ldmatrix_x4(r0, r1, r2, r3, addr);
                    b[ng*2+0][0] = r0; b[ng*2+0][1] = r1;
                    b[ng*2+1][0] = r2; b[ng*2+1][1] = r3;
                }
                #pragma unroll
                for (int mi = 0; mi < 4; mi++)
                    #pragma unroll
                    for (int nj = 0; nj < 4; nj++)
                        mma_fp8(co[mi][nj], a[mi][0], a[mi][1], a[mi][2], a[mi][3],
                                b[nj][0], b[nj][1]);
            }
        }
    }

    const int trow = lane >> 2;
    const int tcol = (lane & 3) * 2;
    #pragma unroll
    for (int mi = 0; mi < 4; mi++) {
        const int mbase = row0 + warp_m*64 + mi*16 + trow;
        #pragma unroll
        for (int nj = 0; nj < 4; nj++) {
            const int col = col0 + warp_n*32 + nj*8 + tcol;
            const float b0 = __ldg(bias + col);
            const float b1 = __ldg(bias + col + 1);
            *(float2*)(C + (size_t)mbase*VV + col) =
                make_float2(hi[mi][nj][0] + co[mi][nj][0]*SC_OUT + b0,
                            hi[mi][nj][1] + co[mi][nj][1]*SC_OUT + b1);
            *(float2*)(C + (size_t)(mbase+8)*VV + col) =
                make_float2(hi[mi][nj][2] + co[mi][nj][2]*SC_OUT + b0,
                            hi[mi][nj][3] + co[mi][nj][3]*SC_OUT + b1);
        }
    }
}

// ---------------------------------------------------------------------------
// Host side
// ---------------------------------------------------------------------------
static void run_gat_layer(const float* xin, const float* a,
                          const float* ow, const float* ob, float* xout,
                          float* wx, float* ssrc, float* sdst, float* agg,
                          __nv_bfloat16* Ap, __nv_bfloat16* Wp,
                          const float* Wl)
{
    dim3 gg(NN/128, DD/128);
    conv_B_k<<<(DD*(DD/4))/256, 256>>>(Wl, Wp);
    conv_A_k<<<(NN*(DD/4))/256, 256>>>(xin, Ap);
    gat_mma_k<0><<<gg, 256, G_SMEM>>>(Ap, Wp, nullptr, wx);
    scores_k<<<(NN*HH*32)/256, 256>>>(wx, a, ssrc, sdst);
    attn_k<<<NN, 128>>>(wx, ssrc, sdst, agg);
    conv_A_k<<<(NN*(DD/4))/256, 256>>>(agg, Ap);
    conv_B_k<<<(DD*(DD/4))/256, 256>>>(ow, Wp);
    gat_mma_k<1><<<gg, 256, G_SMEM>>>(Ap, Wp, ob, xout);
}

extern "C" void kernel_launch(void* const* d_in, const int* in_sizes, int n_in,
                              void* d_out, int out_size)
{
    const int*   ids = (const int*)  d_in[0];
    const float* emb = (const float*)d_in[1];
    const float* W1  = (const float*)d_in[2];
    const float* a1  = (const float*)d_in[3];
    const float* o1w = (const float*)d_in[4];
    const float* o1b = (const float*)d_in[5];
    const float* W2  = (const float*)d_in[6];
    const float* a2  = (const float*)d_in[7];
    const float* o2w = (const float*)d_in[8];
    const float* o2b = (const float*)d_in[9];
    const float* lmw = (const float*)d_in[10];
    const float* lmb = (const float*)d_in[11];
    float* out = (float*)d_out;

    float *px, *px2, *pwx, *pagg, *pssrc, *psdst;
    __nv_bfloat16 *pAp, *pWp, *pAh, *pBh;
    uint8_t *pAc, *pBc;
    cudaGetSymbolAddress((void**)&px,    g_x);
    cudaGetSymbolAddress((void**)&px2,   g_x2);
    cudaGetSymbolAddress((void**)&pwx,   g_wx);
    cudaGetSymbolAddress((void**)&pagg,  g_agg);
    cudaGetSymbolAddress((void**)&pssrc, g_ssrc);
    cudaGetSymbolAddress((void**)&psdst, g_sdst);
    cudaGetSymbolAddress((void**)&pAp,   g_Ap);
    cudaGetSymbolAddress((void**)&pWp,   g_Wp);
    cudaGetSymbolAddress((void**)&pAh,   g_Ah);
    cudaGetSymbolAddress((void**)&pAc,   g_Ac);
    cudaGetSymbolAddress((void**)&pBh,   g_Bh);
    cudaGetSymbolAddress((void**)&pBc,   g_Bc);

    static bool attr_set = false;
    if (!attr_set) {
        cudaFuncSetAttribute(lmhead_k,     cudaFuncAttributeMaxDynamicSharedMemorySize, L_SMEM);
        cudaFuncSetAttribute(gat_mma_k<0>, cudaFuncAttributeMaxDynamicSharedMemorySize, G_SMEM);
        cudaFuncSetAttribute(gat_mma_k<1>, cudaFuncAttributeMaxDynamicSharedMemorySize, G_SMEM);
        attr_set = true;
    }

    // LM-head weight conversion (bf16 hi + fp8 corr)
    conv_lmB_k<<<(VV*(DD/4))/256, 256>>>(lmw, pBh, pBc);
    // Embedding gather
    gather_k<<<(NN*DD/4)/256, 256>>>(ids, emb, px);

    run_gat_layer(px,  a1, o1w, o1b, px2, pwx, pssrc, psdst, pagg, pAp, pWp, W1);
    run_gat_layer(px2, a2, o2w, o2b, px,  pwx, pssrc, psdst, pagg, pAp, pWp, W2);

    // LM-head activation conversion
    conv_lmA_k<<<(NN*(DD/4))/256, 256>>>(px, pAh, pAc);

    // LM head: grid.x = M blocks (fast-varying -> B-tile L2 reuse)
    dim3 g(NN/128, VV/128);
    lmhead_k<<<g, 256, L_SMEM>>>(pAh, pBh, pAc, pBc, lmb, out);
}

// round 10
// speedup vs baseline: 1.2646x; 1.2646x over previous
#include <cuda_runtime.h>
#include <cuda_bf16.h>
#include <math.h>
#include <stdint.h>

// Problem constants (fixed by the reference)
#define BB 2
#define SS 2048
#define DD 512
#define VV 32000
#define HH 4
#define DH 128
#define WW 3
#define NN (BB*SS)   // 4096
#define KP 1536      // GAT split-bf16 K' = 3*512
#define NCH_GAT 24   // KP / 64
#define NCH_LM  8    // 512 / 64 (fused 3-product loop)

// Scratch (device globals; no allocation allowed)
__device__ float g_wx  [NN*DD];
__device__ float g_ssrc[NN*HH];
__device__ float g_sdst[NN*HH];
__device__ __nv_bfloat16 g_Ap [(size_t)NN*KP];   // GAT A split [Ah|Ah|Al]
__device__ __nv_bfloat16 g_Ap2[(size_t)NN*KP];   // GAT A split (layer hand-off)
__device__ __nv_bfloat16 g_Wp [(size_t)DD*KP];   // GAT W split [Bh|Bl|Bh]
__device__ __nv_bfloat16 g_Ah [(size_t)NN*DD];   // LM head A hi
__device__ __nv_bfloat16 g_Al [(size_t)NN*DD];   // LM head A lo
__device__ __nv_bfloat16 g_Bh [(size_t)VV*DD];   // LM head B hi
__device__ __nv_bfloat16 g_Bl [(size_t)VV*DD];   // LM head B lo

// ---------------------------------------------------------------------------
// PTX helpers (sm_80-era: cp.async, ldmatrix, mma.sync — valid at compute_103.
// tcgen05 is NOT available at the harness's virtual PTX target.)
// ---------------------------------------------------------------------------
__device__ __forceinline__ uint32_t smem_u32(const void* p) {
    uint32_t a;
    asm("{ .reg .u64 t; cvta.to.shared.u64 t, %1; cvt.u32.u64 %0, t; }"
        : "=r"(a) : "l"(p));
    return a;
}
__device__ __forceinline__ void cp_async16(uint32_t dst, const void* src) {
    asm volatile("cp.async.cg.shared.global [%0], [%1], 16;\n" :: "r"(dst), "l"(src));
}
#define CP_COMMIT() asm volatile("cp.async.commit_group;\n" ::: "memory")
template<int Nw> __device__ __forceinline__ void cp_wait() {
    asm volatile("cp.async.wait_group %0;\n" :: "n"(Nw) : "memory");
}
__device__ __forceinline__ void ldmatrix_x4(uint32_t& r0, uint32_t& r1,
                                            uint32_t& r2, uint32_t& r3, uint32_t addr) {
    asm volatile("ldmatrix.sync.aligned.m8n8.x4.shared.b16 {%0,%1,%2,%3}, [%4];\n"
                 : "=r"(r0), "=r"(r1), "=r"(r2), "=r"(r3) : "r"(addr));
}
__device__ __forceinline__ void mma_bf16(float* c,
                                         uint32_t a0, uint32_t a1, uint32_t a2, uint32_t a3,
                                         uint32_t b0, uint32_t b1) {
    asm volatile(
        "mma.sync.aligned.m16n8k16.row.col.f32.bf16.bf16.f32 "
        "{%0,%1,%2,%3}, {%4,%5,%6,%7}, {%8,%9}, {%0,%1,%2,%3};\n"
        : "+f"(c[0]), "+f"(c[1]), "+f"(c[2]), "+f"(c[3])
        : "r"(a0), "r"(a1), "r"(a2), "r"(a3), "r"(b0), "r"(b1));
}

// ---------------------------------------------------------------------------
// Fused embedding gather + GAT split: Ap[n] = [h(emb)|h(emb)|l(emb)]
// ---------------------------------------------------------------------------
__global__ void gather_split_k(const int* __restrict__ ids,
                               const float* __restrict__ emb,
                               __nv_bfloat16* __restrict__ Ap)
{
    int idx = blockIdx.x * blockDim.x + threadIdx.x;   // over NN*(DD/4)
    int n  = idx / (DD/4);
    int c  = (idx % (DD/4)) * 4;
    float4 v = *(const float4*)(emb + (size_t)ids[n]*DD + c);
    float f[4] = {v.x, v.y, v.z, v.w};
    __nv_bfloat16 h[4], l[4];
    #pragma unroll
    for (int j = 0; j < 4; j++) {
        h[j] = __float2bfloat16(f[j]);
        l[j] = __float2bfloat16(f[j] - __bfloat162float(h[j]));
    }
    __nv_bfloat16* base = Ap + (size_t)n*KP + c;
    *(__nv_bfloat162*)(base)        = __halves2bfloat162(h[0], h[1]);
    *(__nv_bfloat162*)(base+2)      = __halves2bfloat162(h[2], h[3]);
    *(__nv_bfloat162*)(base+512)    = __halves2bfloat162(h[0], h[1]);
    *(__nv_bfloat162*)(base+514)    = __halves2bfloat162(h[2], h[3]);
    *(__nv_bfloat162*)(base+1024)   = __halves2bfloat162(l[0], l[1]);
    *(__nv_bfloat162*)(base+1026)   = __halves2bfloat162(l[2], l[3]);
}

// ---------------------------------------------------------------------------
// GAT weight split: Wp[r] = [h|l|h]
// ---------------------------------------------------------------------------
__global__ void conv_B_k(const float* __restrict__ src, __nv_bfloat16* __restrict__ dst)
{
    size_t i = (size_t)blockIdx.x * blockDim.x + threadIdx.x;
    size_t r = i / (DD/4);
    int c = (int)(i % (DD/4)) * 4;
    float4 v = *(const float4*)(src + r*DD + c);
    float f[4] = {v.x, v.y, v.z, v.w};
    __nv_bfloat16* base = dst + r*KP + c;
    #pragma unroll
    for (int j = 0; j < 4; j++) {
        __nv_bfloat16 h = __float2bfloat16(f[j]);
        __nv_bfloat16 l = __float2bfloat16(f[j] - __bfloat162float(h));
        base[j]        = h;
        base[512 + j]  = l;
        base[1024 + j] = h;
    }
}

// ---------------------------------------------------------------------------
// LM-head weight split: fp32 -> (hi, lo) bf16 arrays
// ---------------------------------------------------------------------------
__global__ void conv_hl_k(const float* __restrict__ src,
                          __nv_bfloat16* __restrict__ dh, __nv_bfloat16* __restrict__ dl)
{
    size_t i = (size_t)blockIdx.x * blockDim.x + threadIdx.x;
    size_t r = i / (DD/4);
    int c = (int)(i % (DD/4)) * 4;
    float4 v = *(const float4*)(src + r*DD + c);
    float f[4] = {v.x, v.y, v.z, v.w};
    #pragma unroll
    for (int j = 0; j < 4; j++) {
        __nv_bfloat16 h = __float2bfloat16(f[j]);
        __nv_bfloat16 l = __float2bfloat16(f[j] - __bfloat162float(h));
        dh[r*DD + c + j] = h;
        dl[r*DD + c + j] = l;
    }
}

// ---------------------------------------------------------------------------
// Per-node attention scores
// ---------------------------------------------------------------------------
__global__ void scores_k(const float* __restrict__ wx,
                         const float* __restrict__ a,
                         float* __restrict__ ssrc,
                         float* __restrict__ sdst)
{
    int w    = (blockIdx.x * blockDim.x + threadIdx.x) >> 5;
    int lane = threadIdx.x & 31;
    if (w >= NN*HH) return;
    int n = w / HH, h = w % HH;
    const float* row = wx + (size_t)n*DD + h*DH;
    const float* au  = a + (size_t)h*2*DH;
    const float* av  = au + DH;

    int d = lane * 4;
    float4 x = *(const float4*)(row + d);
    float4 u = *(const float4*)(au  + d);
    float4 v = *(const float4*)(av  + d);
    float s1 = x.x*u.x + x.y*u.y + x.z*u.z + x.w*u.w;
    float s2 = x.x*v.x + x.y*v.y + x.z*v.z + x.w*v.w;
    #pragma unroll
    for (int o = 16; o; o >>= 1) {
        s1 += __shfl_xor_sync(0xffffffffu, s1, o);
        s2 += __shfl_xor_sync(0xffffffffu, s2, o);
    }
    if (lane == 0) { ssrc[w] = s1; sdst[w] = s2; }
}

// ---------------------------------------------------------------------------
// Windowed GAT aggregation, fused with GAT split output:
// Ap[n] = [h(agg)|h(agg)|l(agg)]
// ---------------------------------------------------------------------------
__global__ void attn_split_k(const float* __restrict__ wx,
                             const float* __restrict__ ssrc,
                             const float* __restrict__ sdst,
                             __nv_bfloat16* __restrict__ Ap)
{
    int n    = blockIdx.x;
    int h    = threadIdx.x >> 5;
    int lane = threadIdx.x & 31;
    int i    = n % SS;

    float sd = sdst[(size_t)n*HH + h];

    float e[2*WW];
    int   jn[2*WW];
    int cnt = 0;
    #pragma unroll
    for (int off = -WW; off <= WW; off++) {
        if (off == 0) continue;
        int ji = i + off;
        if (ji < 0 || ji >= SS) continue;
        int j = n + off;
        float v = ssrc[(size_t)j*HH + h] + sd;
        v = v >= 0.f ? v : 0.2f * v;
        e[cnt] = v; jn[cnt] = j; cnt++;
    }
    float m = -1e30f;
    for (int c = 0; c < cnt; c++) m = fmaxf(m, e[c]);
    float den = 0.f;
    for (int c = 0; c < cnt; c++) { e[c] = expf(e[c] - m); den += e[c]; }
    float inv = 1.f / (den + 1e-16f);

    int d = lane * 4;
    float acc[4] = {0.f, 0.f, 0.f, 0.f};
    for (int c = 0; c < cnt; c++) {
        const float4 xv = *(const float4*)(wx + (size_t)jn[c]*DD + h*DH + d);
        float al = e[c] * inv;
        acc[0] = fmaf(al, xv.x, acc[0]);
        acc[1] = fmaf(al, xv.y, acc[1]);
        acc[2] = fmaf(al, xv.z, acc[2]);
        acc[3] = fmaf(al, xv.w, acc[3]);
    }
    __nv_bfloat16 hh[4], ll[4];
    #pragma unroll
    for (int q = 0; q < 4; q++) {
        hh[q] = __float2bfloat16(acc[q]);
        ll[q] = __float2bfloat16(acc[q] - __bfloat162float(hh[q]));
    }
    __nv_bfloat16* base = Ap + (size_t)n*KP + h*DH + d;
    *(__nv_bfloat162*)(base)      = __halves2bfloat162(hh[0], hh[1]);
    *(__nv_bfloat162*)(base+2)    = __halves2bfloat162(hh[2], hh[3]);
    *(__nv_bfloat162*)(base+512)  = __halves2bfloat162(hh[0], hh[1]);
    *(__nv_bfloat162*)(base+514)  = __halves2bfloat162(hh[2], hh[3]);
    *(__nv_bfloat162*)(base+1024) = __halves2bfloat162(ll[0], ll[1]);
    *(__nv_bfloat162*)(base+1026) = __halves2bfloat162(ll[2], ll[3]);
}

// ---------------------------------------------------------------------------
// GAT mma GEMM (split-bf16 K'=1536) with fused epilogues:
// EMIT 0: raw fp32 -> Cf (wx)
// EMIT 1: bias+ELU -> GAT split [h|h|l] into Cp (KP layout, next layer input)
// EMIT 2: bias+ELU -> lmhead hi/lo into Ch/Cl (DD layout)
// ---------------------------------------------------------------------------
#define G_STAGES 3
#define G_STAGE_BYTES 32768
#define G_SMEM (G_STAGES*G_STAGE_BYTES)

__device__ __forceinline__ void load_stage_gat(
    const __nv_bfloat16* __restrict__ Ap, const __nv_bfloat16* __restrict__ Bp,
    int row0, int col0, int k0, uint32_t stage_base, int tid)
{
    #pragma unroll
    for (int it = 0; it < 8; it++) {
        int g = tid + it*256;
        bool isA = (g < 1024);
        int gg  = isA ? g : (g - 1024);
        int row = gg >> 3;
        int gran = gg & 7;
        const __nv_bfloat16* src = isA
            ? (Ap + (size_t)(row0 + row)*KP + k0 + gran*8)
            : (Bp + (size_t)(col0 + row)*KP + k0 + gran*8);
        uint32_t dst = stage_base + (isA ? 0u : 16384u)
                     + (uint32_t)row*128u + (uint32_t)((gran ^ (row & 7)) << 4);
        cp_async16(dst, src);
    }
}

template<int EMIT>
__global__ void __launch_bounds__(256, 2)
gat_mma_k(const __nv_bfloat16* __restrict__ Ap,
          const __nv_bfloat16* __restrict__ Bp,
          const float* __restrict__ bias,
          float* __restrict__ Cf,
          __nv_bfloat16* __restrict__ Cp,
          __nv_bfloat16* __restrict__ Ch,
          __nv_bfloat16* __restrict__ Cl)
{
    extern __shared__ char smem[];
    const uint32_t sb = smem_u32(smem);
    const int tid  = threadIdx.x;
    const int wid  = tid >> 5;
    const int lane = tid & 31;
    const int row0 = blockIdx.x * 128;
    const int col0 = blockIdx.y * 128;

    const int warp_m = wid & 3;
    const int warp_n = wid >> 2;

    float acc[2][8][4];
    #pragma unroll
    for (int i = 0; i < 2; i++)
        #pragma unroll
        for (int j = 0; j < 8; j++)
            #pragma unroll
            for (int q = 0; q < 4; q++) acc[i][j][q] = 0.f;

    load_stage_gat(Ap, Bp, row0, col0, 0,  sb,                 tid); CP_COMMIT();
    load_stage_gat(Ap, Bp, row0, col0, 64, sb + G_STAGE_BYTES, tid); CP_COMMIT();

    const int a_row  = warp_m*32 + (lane & 15);
    const int a_gsel = lane >> 4;
    const int b_row  = warp_n*64 + ((lane >> 4) << 3) + (lane & 7);
    const int b_gsel = (lane >> 3) & 1;

    for (int c = 0; c < NCH_GAT; c++) {
        cp_wait<G_STAGES-2>();
        __syncthreads();

        if (c + 2 < NCH_GAT)
            load_stage_gat(Ap, Bp, row0, col0, (c+2)*64,
                           sb + ((c+2)%G_STAGES)*G_STAGE_BYTES, tid);
        CP_COMMIT();

        const uint32_t sA = sb + (c%G_STAGES)*G_STAGE_BYTES;
        const uint32_t sB = sA + 16384u;

        #pragma unroll
        for (int s = 0; s < 4; s++) {
            uint32_t a[2][4];
            #pragma unroll
            for (int mi = 0; mi < 2; mi++) {
                int r = a_row + mi*16;
                int gran = 2*s + a_gsel;
                uint32_t addr = sA + (uint32_t)r*128u + (uint32_t)((gran ^ (r & 7)) << 4);
                ldmatrix_x4(a[mi][0], a[mi][1], a[mi][2], a[mi][3], addr);
            }
            uint32_t b[8][2];
            #pragma unroll
            for (int ng = 0; ng < 4; ng++) {
                int r = b_row + ng*16;
                int gran = 2*s + b_gsel;
                uint32_t addr = sB + (uint32_t)r*128u + (uint32_t)((gran ^ (r & 7)) << 4);
                uint32_t r0, r1, r2, r3;
                ldmatrix_x4(r0, r1, r2, r3, addr);
                b[ng*2+0][0] = r0; b[ng*2+0][1] = r1;
                b[ng*2+1][0] = r2; b[ng*2+1][1] = r3;
            }
            #pragma unroll
            for (int mi = 0; mi < 2; mi++)
                #pragma unroll
                for (int nj = 0; nj < 8; nj++)
                    mma_bf16(acc[mi][nj], a[mi][0], a[mi][1], a[mi][2], a[mi][3],
                             b[nj][0], b[nj][1]);
        }
    }

    const int trow = lane >> 2;
    const int tcol = (lane & 3) * 2;
    #pragma unroll
    for (int mi = 0; mi < 2; mi++) {
        const int mbase = row0 + warp_m*32 + mi*16 + trow;
        #pragma unroll
        for (int nj = 0; nj < 8; nj++) {
            const int col = col0 + warp_n*64 + nj*8 + tcol;
            float vv[4] = {acc[mi][nj][0], acc[mi][nj][1], acc[mi][nj][2], acc[mi][nj][3]};
            if (EMIT == 0) {
                *(float2*)(Cf + (size_t)mbase*DD + col)     = make_float2(vv[0], vv[1]);
                *(float2*)(Cf + (size_t)(mbase+8)*DD + col) = make_float2(vv[2], vv[3]);
            } else {
                const float b0 = __ldg(bias + col);
                const float b1 = __ldg(bias + col + 1);
                vv[0] += b0; vv[1] += b1; vv[2] += b0; vv[3] += b1;
                #pragma unroll
                for (int q = 0; q < 4; q++)
                    vv[q] = vv[q] > 0.f ? vv[q] : (expf(vv[q]) - 1.f);
                __nv_bfloat16 h[4], l[4];
                #pragma unroll
                for (int q = 0; q < 4; q++) {
                    h[q] = __float2bfloat16(vv[q]);
                    l[q] = __float2bfloat16(vv[q] - __bfloat162float(h[q]));
                }
                if (EMIT == 1) {
                    __nv_bfloat16* r0p = Cp + (size_t)mbase*KP + col;
                    __nv_bfloat16* r1p = Cp + (size_t)(mbase+8)*KP + col;
                    *(__nv_bfloat162*)(r0p)      = __halves2bfloat162(h[0], h[1]);
                    *(__nv_bfloat162*)(r0p+512)  = __halves2bfloat162(h[0], h[1]);
                    *(__nv_bfloat162*)(r0p+1024) = __halves2bfloat162(l[0], l[1]);
                    *(__nv_bfloat162*)(r1p)      = __halves2bfloat162(h[2], h[3]);
                    *(__nv_bfloat162*)(r1p+512)  = __halves2bfloat162(h[2], h[3]);
                    *(__nv_bfloat162*)(r1p+1024) = __halves2bfloat162(l[2], l[3]);
                } else {  // EMIT == 2
                    *(__nv_bfloat162*)(Ch + (size_t)mbase*DD + col) =
                        __halves2bfloat162(h[0], h[1]);
                    *(__nv_bfloat162*)(Cl + (size_t)mbase*DD + col) =
                        __halves2bfloat162(l[0], l[1]);
                    *(__nv_bfloat162*)(Ch + (size_t)(mbase+8)*DD + col) =
                        __halves2bfloat162(h[2], h[3]);
                    *(__nv_bfloat162*)(Cl + (size_t)(mbase+8)*DD + col) =
                        __halves2bfloat162(l[2], l[3]);
                }
            }
        }
    }
}

// ---------------------------------------------------------------------------
// LM head v5 (Round-7 best): fused 3-product split-bf16 with shared fragments.
// C = Ah@Bh^T + Ah@Bl^T + Al@Bh^T + bias, ONE K loop (8 chunks of 64).
// CTA 128x256, 8 warps of 64x64, 2-stage.
// ---------------------------------------------------------------------------
#define L_STAGES 2
#define L_STAGE_BYTES 98304   // Ah 16K + Al 16K + Bh 32K + Bl 32K
#define L_SMEM (L_STAGES*L_STAGE_BYTES)
#define L_OFF_AL 16384u
#define L_OFF_BH 32768u
#define L_OFF_BL 65536u

__device__ __forceinline__ void load_stage_lm(
    const __nv_bfloat16* __restrict__ Ah, const __nv_bfloat16* __restrict__ Al,
    const __nv_bfloat16* __restrict__ Bh, const __nv_bfloat16* __restrict__ Bl,
    int row0, int col0, int kk, uint32_t stage_base, int tid)
{
    #pragma unroll
    for (int it = 0; it < 24; it++) {
        int g = tid + it*256;              // 0..6143 granules of 16B
        const __nv_bfloat16* basep;
        uint32_t soff;
        int gg;
        if (g < 2048) {                    // A: 2 x 1024 granules
            gg = g & 1023;
            basep = (g < 1024 ? Ah : Al) + (size_t)(row0 + (gg >> 3))*DD;
            soff  = (g < 1024 ? 0u : L_OFF_AL);
        } else {                           // B: 2 x 2048 granules
            int h = g - 2048;
            gg = h & 2047;
            basep = (h < 2048 ? Bh : Bl) + (size_t)(col0 + (gg >> 3))*DD;
            soff  = (h < 2048 ? L_OFF_BH : L_OFF_BL);
        }
        int row  = gg >> 3;
        int gran = gg & 7;
        uint32_t dst = stage_base + soff
                     + (uint32_t)row*128u + (uint32_t)((gran ^ (row & 7)) << 4);
        cp_async16(dst, basep + kk + gran*8);
    }
}

__global__ void __launch_bounds__(256, 1)
lmhead_k(const __nv_bfloat16* __restrict__ Ah,
         const __nv_bfloat16* __restrict__ Al,
         const __nv_bfloat16* __restrict__ Bh,
         const __nv_bfloat16* __restrict__ Bl,
         const float* __restrict__ bias,
         float* __restrict__ C)
{
    extern __shared__ char smem[];
    const uint32_t sb = smem_u32(smem);
    const int tid  = threadIdx.x;
    const int wid  = tid >> 5;
    const int lane = tid & 31;
    const int row0 = blockIdx.x * 128;
    const int col0 = blockIdx.y * 256;

    const int warp_m = wid & 1;      // 2(m) x 4(n) warps; warp tile 64x64
    const int warp_n = wid >> 1;

    float acc[4][8][4];
    #pragma unroll
    for (int i = 0; i < 4; i++)
        #pragma unroll
        for (int j = 0; j < 8; j++)
            #pragma unroll
            for (int q = 0; q < 4; q++) acc[i][j][q] = 0.f;

    // prologue: chunk 0 -> stage 0
    load_stage_lm(Ah, Al, Bh, Bl, row0, col0, 0, sb, tid);
    CP_COMMIT();

    const int a_row  = warp_m*64 + (lane & 15);
    const int a_gsel = lane >> 4;
    const int b_row  = warp_n*64 + ((lane >> 4) << 3) + (lane & 7);
    const int b_gsel = (lane >> 3) & 1;

    for (int c = 0; c < NCH_LM; c++) {
        // prefetch next chunk into the other stage
        if (c + 1 < NCH_LM)
            load_stage_lm(Ah, Al, Bh, Bl, row0, col0, (c+1)*64,
                          sb + ((c+1)&1)*L_STAGE_BYTES, tid);
        CP_COMMIT();
        cp_wait<1>();      // chunk c landed (the c+1 group may be in flight)
        __syncthreads();

        const uint32_t st  = sb + (c&1)*L_STAGE_BYTES;
        const uint32_t sAh = st;
        const uint32_t sAl = st + L_OFF_AL;
        const uint32_t sBh = st + L_OFF_BH;
        const uint32_t sBl = st + L_OFF_BL;

        #pragma unroll
        for (int s = 0; s < 4; s++) {   // four k16 steps per 64-chunk
            uint32_t aH[4][4], aL[4][4];
            #pragma unroll
            for (int mi = 0; mi < 4; mi++) {
                int r = a_row + mi*16;
                int g = 2*s + a_gsel;
                uint32_t sw = (uint32_t)r*128u + (uint32_t)((g ^ (r & 7)) << 4);
                ldmatrix_x4(aH[mi][0], aH[mi][1], aH[mi][2], aH[mi][3], sAh + sw);
                ldmatrix_x4(aL[mi][0], aL[mi][1], aL[mi][2], aL[mi][3], sAl + sw);
            }
            uint32_t bH[8][2], bL[8][2];
            #pragma unroll
            for (int ng = 0; ng < 4; ng++) {
                int r = b_row + ng*16;
                int g = 2*s + b_gsel;
                uint32_t sw = (uint32_t)r*128u + (uint32_t)((g ^ (r & 7)) << 4);
                uint32_t r0, r1, r2, r3;
                ldmatrix_x4(r0, r1, r2, r3, sBh + sw);
                bH[ng*2+0][0] = r0; bH[ng*2+0][1] = r1;
                bH[ng*2+1][0] = r2; bH[ng*2+1][1] = r3;
                ldmatrix_x4(r0, r1, r2, r3, sBl + sw);
                bL[ng*2+0][0] = r0; bL[ng*2+0][1] = r1;
                bL[ng*2+1][0] = r2; bL[ng*2+1][1] = r3;
            }
            // three products, shared fragments
            #pragma unroll
            for (int mi = 0; mi < 4; mi++)
                #pragma unroll
                for (int nj = 0; nj < 8; nj++) {
                    mma_bf16(acc[mi][nj], aH[mi][0], aH[mi][1], aH[mi][2], aH[mi][3],
                             bH[nj][0], bH[nj][1]);
                    mma_bf16(acc[mi][nj], aH[mi][0], aH[mi][1], aH[mi][2], aH[mi][3],
                             bL[nj][0], bL[nj][1]);
                    mma_bf16(acc[mi][nj], aL[mi][0], aL[mi][1], aL[mi][2], aL[mi][3],
                             bH[nj][0], bH[nj][1]);
                }
        }
        __syncthreads();   // stage consumed before refill next iteration
    }

    const int trow = lane >> 2;
    const int tcol = (lane & 3) * 2;
    #pragma unroll
    for (int mi = 0; mi < 4; mi++) {
        const int mbase = row0 + warp_m*64 + mi*16 + trow;
        #pragma unroll
        for (int nj = 0; nj < 8; nj++) {
            const int col = col0 + warp_n*64 + nj*8 + tcol;
            const float b0 = __ldg(bias + col);
            const float b1 = __ldg(bias + col + 1);
            *(float2*)(C + (size_t)mbase*VV + col) =
                make_float2(acc[mi][nj][0] + b0, acc[mi][nj][1] + b1);
            *(float2*)(C + (size_t)(mbase+8)*VV + col) =
                make_float2(acc[mi][nj][2] + b0, acc[mi][nj][3] + b1);
        }
    }
}

// ---------------------------------------------------------------------------
// Host side
// ---------------------------------------------------------------------------
extern "C" void kernel_launch(void* const* d_in, const int* in_sizes, int n_in,
                              void* d_out, int out_size)
{
    const int*   ids = (const int*)  d_in[0];
    const float* emb = (const float*)d_in[1];
    const float* W1  = (const float*)d_in[2];
    const float* a1  = (const float*)d_in[3];
    const float* o1w = (const float*)d_in[4];
    const float* o1b = (const float*)d_in[5];
    const float* W2  = (const float*)d_in[6];
    const float* a2  = (const float*)d_in[7];
    const float* o2w = (const float*)d_in[8];
    const float* o2b = (const float*)d_in[9];
    const float* lmw = (const float*)d_in[10];
    const float* lmb = (const float*)d_in[11];
    float* out = (float*)d_out;

    float *pwx, *pssrc, *psdst;
    __nv_bfloat16 *pAp, *pAp2, *pWp, *pAh, *pAl, *pBh, *pBl;
    cudaGetSymbolAddress((void**)&pwx,   g_wx);
    cudaGetSymbolAddress((void**)&pssrc, g_ssrc);
    cudaGetSymbolAddress((void**)&psdst, g_sdst);
    cudaGetSymbolAddress((void**)&pAp,   g_Ap);
    cudaGetSymbolAddress((void**)&pAp2,  g_Ap2);
    cudaGetSymbolAddress((void**)&pWp,   g_Wp);
    cudaGetSymbolAddress((void**)&pAh,   g_Ah);
    cudaGetSymbolAddress((void**)&pAl,   g_Al);
    cudaGetSymbolAddress((void**)&pBh,   g_Bh);
    cudaGetSymbolAddress((void**)&pBl,   g_Bl);

    static bool attr_set = false;
    if (!attr_set) {
        cudaFuncSetAttribute(lmhead_k,     cudaFuncAttributeMaxDynamicSharedMemorySize, L_SMEM);
        cudaFuncSetAttribute(gat_mma_k<0>, cudaFuncAttributeMaxDynamicSharedMemorySize, G_SMEM);
        cudaFuncSetAttribute(gat_mma_k<1>, cudaFuncAttributeMaxDynamicSharedMemorySize, G_SMEM);
        cudaFuncSetAttribute(gat_mma_k<2>, cudaFuncAttributeMaxDynamicSharedMemorySize, G_SMEM);
        attr_set = true;
    }

    const dim3 gg(NN/128, DD/128);
    const int conv_w_blocks = (DD*(DD/4))/256;

    // LM-head weight split (hi/lo)
    conv_hl_k<<<(VV*(DD/4))/256, 256>>>(lmw, pBh, pBl);
    // Fused gather + GAT split (layer-1 GEMM1 input)
    gather_split_k<<<(NN*(DD/4))/256, 256>>>(ids, emb, pAp);

    // ---- Layer 1 ----
    conv_B_k<<<conv_w_blocks, 256>>>(W1, pWp);
    gat_mma_k<0><<<gg, 256, G_SMEM>>>(pAp, pWp, nullptr, pwx, nullptr, nullptr, nullptr);
    scores_k<<<(NN*HH*32)/256, 256>>>(pwx, a1, pssrc, psdst);
    attn_split_k<<<NN, 128>>>(pwx, pssrc, psdst, pAp);
    conv_B_k<<<conv_w_blocks, 256>>>(o1w, pWp);
    gat_mma_k<1><<<gg, 256, G_SMEM>>>(pAp, pWp, o1b, nullptr, pAp2, nullptr, nullptr);

    // ---- Layer 2 ----
    conv_B_k<<<conv_w_blocks, 256>>>(W2, pWp);
    gat_mma_k<0><<<gg, 256, G_SMEM>>>(pAp2, pWp, nullptr, pwx, nullptr, nullptr, nullptr);
    scores_k<<<(NN*HH*32)/256, 256>>>(pwx, a2, pssrc, psdst);
    attn_split_k<<<NN, 128>>>(pwx, pssrc, psdst, pAp);
    conv_B_k<<<conv_w_blocks, 256>>>(o2w, pWp);
    gat_mma_k<2><<<gg, 256, G_SMEM>>>(pAp, pWp, o2b, nullptr, nullptr, pAh, pAl);

    // ---- LM head (grid.x = M blocks fast-varying -> B-tile L2 reuse) ----
    dim3 g(NN/128, VV/256);
    lmhead_k<<<g, 256, L_SMEM>>>(pAh, pAl, pBh, pBl, lmb, out);
}

// round 11
// speedup vs baseline: 1.5871x; 1.2551x over previous
#include <cuda_runtime.h>
#include <cuda_bf16.h>
#include <math.h>
#include <stdint.h>

// Problem constants (fixed by the reference)
#define BB 2
#define SS 2048
#define DD 512
#define VV 32000
#define HH 4
#define DH 128
#define WW 3
#define NN (BB*SS)   // 4096
#define KP 1536      // GAT split-bf16 K' = 3*512
#define NCH_GAT 24   // KP / 64
#define NCH_LM  16   // 512 / 32 (tf32, 32 elements = 128B per chunk row)

// Scratch (device globals; no allocation allowed)
__device__ float g_wx  [NN*DD];
__device__ float g_ssrc[NN*HH];
__device__ float g_sdst[NN*HH];
__device__ __nv_bfloat16 g_Ap [(size_t)NN*KP];   // GAT A split [Ah|Ah|Al]
__device__ __nv_bfloat16 g_Ap2[(size_t)NN*KP];   // GAT A split (layer hand-off)
__device__ __nv_bfloat16 g_Wp [(size_t)DD*KP];   // GAT W split [Bh|Bl|Bh]
__device__ uint32_t g_At [(size_t)NN*DD];        // LM head A (tf32 bits)
__device__ uint32_t g_Bt [(size_t)VV*DD];        // LM head B (tf32 bits)

// ---------------------------------------------------------------------------
// PTX helpers (sm_80-era: cp.async, ldmatrix, mma.sync — valid at compute_103.
// tcgen05 is NOT available at the harness's virtual PTX target.)
// ---------------------------------------------------------------------------
__device__ __forceinline__ uint32_t smem_u32(const void* p) {
    uint32_t a;
    asm("{ .reg .u64 t; cvta.to.shared.u64 t, %1; cvt.u32.u64 %0, t; }"
        : "=r"(a) : "l"(p));
    return a;
}
__device__ __forceinline__ void cp_async16(uint32_t dst, const void* src) {
    asm volatile("cp.async.cg.shared.global [%0], [%1], 16;\n" :: "r"(dst), "l"(src));
}
#define CP_COMMIT() asm volatile("cp.async.commit_group;\n" ::: "memory")
template<int Nw> __device__ __forceinline__ void cp_wait() {
    asm volatile("cp.async.wait_group %0;\n" :: "n"(Nw) : "memory");
}
__device__ __forceinline__ void ldmatrix_x4(uint32_t& r0, uint32_t& r1,
                                            uint32_t& r2, uint32_t& r3, uint32_t addr) {
    asm volatile("ldmatrix.sync.aligned.m8n8.x4.shared.b16 {%0,%1,%2,%3}, [%4];\n"
                 : "=r"(r0), "=r"(r1), "=r"(r2), "=r"(r3) : "r"(addr));
}
__device__ __forceinline__ void mma_bf16(float* c,
                                         uint32_t a0, uint32_t a1, uint32_t a2, uint32_t a3,
                                         uint32_t b0, uint32_t b1) {
    asm volatile(
        "mma.sync.aligned.m16n8k16.row.col.f32.bf16.bf16.f32 "
        "{%0,%1,%2,%3}, {%4,%5,%6,%7}, {%8,%9}, {%0,%1,%2,%3};\n"
        : "+f"(c[0]), "+f"(c[1]), "+f"(c[2]), "+f"(c[3])
        : "r"(a0), "r"(a1), "r"(a2), "r"(a3), "r"(b0), "r"(b1));
}
// tf32 mma: fragments loaded with the SAME ldmatrix code as bf16 — each 32-bit
// register's two adjacent b16 slots reinterpret as one tf32 at half the k index.
__device__ __forceinline__ void mma_tf32(float* c,
                                         uint32_t a0, uint32_t a1, uint32_t a2, uint32_t a3,
                                         uint32_t b0, uint32_t b1) {
    asm volatile(
        "mma.sync.aligned.m16n8k8.row.col.f32.tf32.tf32.f32 "
        "{%0,%1,%2,%3}, {%4,%5,%6,%7}, {%8,%9}, {%0,%1,%2,%3};\n"
        : "+f"(c[0]), "+f"(c[1]), "+f"(c[2]), "+f"(c[3])
        : "r"(a0), "r"(a1), "r"(a2), "r"(a3), "r"(b0), "r"(b1));
}
__device__ __forceinline__ uint32_t f2tf32(float x) {
    uint32_t r;
    asm("cvt.rna.tf32.f32 %0, %1;" : "=r"(r) : "f"(x));
    return r;
}

// ---------------------------------------------------------------------------
// Fused embedding gather + GAT split: Ap[n] = [h(emb)|h(emb)|l(emb)]
// ---------------------------------------------------------------------------
__global__ void gather_split_k(const int* __restrict__ ids,
                               const float* __restrict__ emb,
                               __nv_bfloat16* __restrict__ Ap)
{
    int idx = blockIdx.x * blockDim.x + threadIdx.x;   // over NN*(DD/4)
    int n  = idx / (DD/4);
    int c  = (idx % (DD/4)) * 4;
    float4 v = *(const float4*)(emb + (size_t)ids[n]*DD + c);
    float f[4] = {v.x, v.y, v.z, v.w};
    __nv_bfloat16 h[4], l[4];
    #pragma unroll
    for (int j = 0; j < 4; j++) {
        h[j] = __float2bfloat16(f[j]);
        l[j] = __float2bfloat16(f[j] - __bfloat162float(h[j]));
    }
    __nv_bfloat16* base = Ap + (size_t)n*KP + c;
    *(__nv_bfloat162*)(base)        = __halves2bfloat162(h[0], h[1]);
    *(__nv_bfloat162*)(base+2)      = __halves2bfloat162(h[2], h[3]);
    *(__nv_bfloat162*)(base+512)    = __halves2bfloat162(h[0], h[1]);
    *(__nv_bfloat162*)(base+514)    = __halves2bfloat162(h[2], h[3]);
    *(__nv_bfloat162*)(base+1024)   = __halves2bfloat162(l[0], l[1]);
    *(__nv_bfloat162*)(base+1026)   = __halves2bfloat162(l[2], l[3]);
}

// ---------------------------------------------------------------------------
// GAT weight split: Wp[r] = [h|l|h]
// ---------------------------------------------------------------------------
__global__ void conv_B_k(const float* __restrict__ src, __nv_bfloat16* __restrict__ dst)
{
    size_t i = (size_t)blockIdx.x * blockDim.x + threadIdx.x;
    size_t r = i / (DD/4);
    int c = (int)(i % (DD/4)) * 4;
    float4 v = *(const float4*)(src + r*DD + c);
    float f[4] = {v.x, v.y, v.z, v.w};
    __nv_bfloat16* base = dst + r*KP + c;
    #pragma unroll
    for (int j = 0; j < 4; j++) {
        __nv_bfloat16 h = __float2bfloat16(f[j]);
        __nv_bfloat16 l = __float2bfloat16(f[j] - __bfloat162float(h));
        base[j]        = h;
        base[512 + j]  = l;
        base[1024 + j] = h;
    }
}

// ---------------------------------------------------------------------------
// LM-head weight conversion: fp32 -> tf32 bits
// ---------------------------------------------------------------------------
__global__ void conv_tf32_k(const float* __restrict__ src, uint32_t* __restrict__ dst)
{
    size_t i = (size_t)blockIdx.x * blockDim.x + threadIdx.x;   // over rows*(DD/4)
    size_t base = i * 4;
    float4 v = *(const float4*)(src + base);
    uint4 o;
    o.x = f2tf32(v.x); o.y = f2tf32(v.y); o.z = f2tf32(v.z); o.w = f2tf32(v.w);
    *(uint4*)(dst + base) = o;
}

// ---------------------------------------------------------------------------
// Per-node attention scores
// ---------------------------------------------------------------------------
__global__ void scores_k(const float* __restrict__ wx,
                         const float* __restrict__ a,
                         float* __restrict__ ssrc,
                         float* __restrict__ sdst)
{
    int w    = (blockIdx.x * blockDim.x + threadIdx.x) >> 5;
    int lane = threadIdx.x & 31;
    if (w >= NN*HH) return;
    int n = w / HH, h = w % HH;
    const float* row = wx + (size_t)n*DD + h*DH;
    const float* au  = a + (size_t)h*2*DH;
    const float* av  = au + DH;

    int d = lane * 4;
    float4 x = *(const float4*)(row + d);
    float4 u = *(const float4*)(au  + d);
    float4 v = *(const float4*)(av  + d);
    float s1 = x.x*u.x + x.y*u.y + x.z*u.z + x.w*u.w;
    float s2 = x.x*v.x + x.y*v.y + x.z*v.z + x.w*v.w;
    #pragma unroll
    for (int o = 16; o; o >>= 1) {
        s1 += __shfl_xor_sync(0xffffffffu, s1, o);
        s2 += __shfl_xor_sync(0xffffffffu, s2, o);
    }
    if (lane == 0) { ssrc[w] = s1; sdst[w] = s2; }
}

// ---------------------------------------------------------------------------
// Windowed GAT aggregation, fused with GAT split output:
// Ap[n] = [h(agg)|h(agg)|l(agg)]
// ---------------------------------------------------------------------------
__global__ void attn_split_k(const float* __restrict__ wx,
                             const float* __restrict__ ssrc,
                             const float* __restrict__ sdst,
                             __nv_bfloat16* __restrict__ Ap)
{
    int n    = blockIdx.x;
    int h    = threadIdx.x >> 5;
    int lane = threadIdx.x & 31;
    int i    = n % SS;

    float sd = sdst[(size_t)n*HH + h];

    float e[2*WW];
    int   jn[2*WW];
    int cnt = 0;
    #pragma unroll
    for (int off = -WW; off <= WW; off++) {
        if (off == 0) continue;
        int ji = i + off;
        if (ji < 0 || ji >= SS) continue;
        int j = n + off;
        float v = ssrc[(size_t)j*HH + h] + sd;
        v = v >= 0.f ? v : 0.2f * v;
        e[cnt] = v; jn[cnt] = j; cnt++;
    }
    float m = -1e30f;
    for (int c = 0; c < cnt; c++) m = fmaxf(m, e[c]);
    float den = 0.f;
    for (int c = 0; c < cnt; c++) { e[c] = expf(e[c] - m); den += e[c]; }
    float inv = 1.f / (den + 1e-16f);

    int d = lane * 4;
    float acc[4] = {0.f, 0.f, 0.f, 0.f};
    for (int c = 0; c < cnt; c++) {
        const float4 xv = *(const float4*)(wx + (size_t)jn[c]*DD + h*DH + d);
        float al = e[c] * inv;
        acc[0] = fmaf(al, xv.x, acc[0]);
        acc[1] = fmaf(al, xv.y, acc[1]);
        acc[2] = fmaf(al, xv.z, acc[2]);
        acc[3] = fmaf(al, xv.w, acc[3]);
    }
    __nv_bfloat16 hh[4], ll[4];
    #pragma unroll
    for (int q = 0; q < 4; q++) {
        hh[q] = __float2bfloat16(acc[q]);
        ll[q] = __float2bfloat16(acc[q] - __bfloat162float(hh[q]));
    }
    __nv_bfloat16* base = Ap + (size_t)n*KP + h*DH + d;
    *(__nv_bfloat162*)(base)      = __halves2bfloat162(hh[0], hh[1]);
    *(__nv_bfloat162*)(base+2)    = __halves2bfloat162(hh[2], hh[3]);
    *(__nv_bfloat162*)(base+512)  = __halves2bfloat162(hh[0], hh[1]);
    *(__nv_bfloat162*)(base+514)  = __halves2bfloat162(hh[2], hh[3]);
    *(__nv_bfloat162*)(base+1024) = __halves2bfloat162(ll[0], ll[1]);
    *(__nv_bfloat162*)(base+1026) = __halves2bfloat162(ll[2], ll[3]);
}

// ---------------------------------------------------------------------------
// GAT mma GEMM (split-bf16 K'=1536) with fused epilogues:
// EMIT 0: raw fp32 -> Cf (wx)
// EMIT 1: bias+ELU -> GAT split [h|h|l] into Cp (KP layout, next layer input)
// EMIT 2: bias+ELU -> tf32 bits into Ct (DD layout, lmhead A input)
// ---------------------------------------------------------------------------
#define G_STAGES 3
#define G_STAGE_BYTES 32768
#define G_SMEM (G_STAGES*G_STAGE_BYTES)

__device__ __forceinline__ void load_stage_gat(
    const __nv_bfloat16* __restrict__ Ap, const __nv_bfloat16* __restrict__ Bp,
    int row0, int col0, int k0, uint32_t stage_base, int tid)
{
    #pragma unroll
    for (int it = 0; it < 8; it++) {
        int g = tid + it*256;
        bool isA = (g < 1024);
        int gg  = isA ? g : (g - 1024);
        int row = gg >> 3;
        int gran = gg & 7;
        const __nv_bfloat16* src = isA
            ? (Ap + (size_t)(row0 + row)*KP + k0 + gran*8)
            : (Bp + (size_t)(col0 + row)*KP + k0 + gran*8);
        uint32_t dst = stage_base + (isA ? 0u : 16384u)
                     + (uint32_t)row*128u + (uint32_t)((gran ^ (row & 7)) << 4);
        cp_async16(dst, src);
    }
}

template<int EMIT>
__global__ void __launch_bounds__(256, 2)
gat_mma_k(const __nv_bfloat16* __restrict__ Ap,
          const __nv_bfloat16* __restrict__ Bp,
          const float* __restrict__ bias,
          float* __restrict__ Cf,
          __nv_bfloat16* __restrict__ Cp,
          uint32_t* __restrict__ Ct)
{
    extern __shared__ char smem[];
    const uint32_t sb = smem_u32(smem);
    const int tid  = threadIdx.x;
    const int wid  = tid >> 5;
    const int lane = tid & 31;
    const int row0 = blockIdx.x * 128;
    const int col0 = blockIdx.y * 128;

    const int warp_m = wid & 3;
    const int warp_n = wid >> 2;

    float acc[2][8][4];
    #pragma unroll
    for (int i = 0; i < 2; i++)
        #pragma unroll
        for (int j = 0; j < 8; j++)
            #pragma unroll
            for (int q = 0; q < 4; q++) acc[i][j][q] = 0.f;

    load_stage_gat(Ap, Bp, row0, col0, 0,  sb,                 tid); CP_COMMIT();
    load_stage_gat(Ap, Bp, row0, col0, 64, sb + G_STAGE_BYTES, tid); CP_COMMIT();

    const int a_row  = warp_m*32 + (lane & 15);
    const int a_gsel = lane >> 4;
    const int b_row  = warp_n*64 + ((lane >> 4) << 3) + (lane & 7);
    const int b_gsel = (lane >> 3) & 1;

    for (int c = 0; c < NCH_GAT; c++) {
        cp_wait<G_STAGES-2>();
        __syncthreads();

        if (c + 2 < NCH_GAT)
            load_stage_gat(Ap, Bp, row0, col0, (c+2)*64,
                           sb + ((c+2)%G_STAGES)*G_STAGE_BYTES, tid);
        CP_COMMIT();

        const uint32_t sA = sb + (c%G_STAGES)*G_STAGE_BYTES;
        const uint32_t sB = sA + 16384u;

        #pragma unroll
        for (int s = 0; s < 4; s++) {
            uint32_t a[2][4];
            #pragma unroll
            for (int mi = 0; mi < 2; mi++) {
                int r = a_row + mi*16;
                int gran = 2*s + a_gsel;
                uint32_t addr = sA + (uint32_t)r*128u + (uint32_t)((gran ^ (r & 7)) << 4);
                ldmatrix_x4(a[mi][0], a[mi][1], a[mi][2], a[mi][3], addr);
            }
            uint32_t b[8][2];
            #pragma unroll
            for (int ng = 0; ng < 4; ng++) {
                int r = b_row + ng*16;
                int gran = 2*s + b_gsel;
                uint32_t addr = sB + (uint32_t)r*128u + (uint32_t)((gran ^ (r & 7)) << 4);
                uint32_t r0, r1, r2, r3;
                ldmatrix_x4(r0, r1, r2, r3, addr);
                b[ng*2+0][0] = r0; b[ng*2+0][1] = r1;
                b[ng*2+1][0] = r2; b[ng*2+1][1] = r3;
            }
            #pragma unroll
            for (int mi = 0; mi < 2; mi++)
                #pragma unroll
                for (int nj = 0; nj < 8; nj++)
                    mma_bf16(acc[mi][nj], a[mi][0], a[mi][1], a[mi][2], a[mi][3],
                             b[nj][0], b[nj][1]);
        }
    }

    const int trow = lane >> 2;
    const int tcol = (lane & 3) * 2;
    #pragma unroll
    for (int mi = 0; mi < 2; mi++) {
        const int mbase = row0 + warp_m*32 + mi*16 + trow;
        #pragma unroll
        for (int nj = 0; nj < 8; nj++) {
            const int col = col0 + warp_n*64 + nj*8 + tcol;
            float vv[4] = {acc[mi][nj][0], acc[mi][nj][1], acc[mi][nj][2], acc[mi][nj][3]};
            if (EMIT == 0) {
                *(float2*)(Cf + (size_t)mbase*DD + col)     = make_float2(vv[0], vv[1]);
                *(float2*)(Cf + (size_t)(mbase+8)*DD + col) = make_float2(vv[2], vv[3]);
            } else {
                const float b0 = __ldg(bias + col);
                const float b1 = __ldg(bias + col + 1);
                vv[0] += b0; vv[1] += b1; vv[2] += b0; vv[3] += b1;
                #pragma unroll
                for (int q = 0; q < 4; q++)
                    vv[q] = vv[q] > 0.f ? vv[q] : (expf(vv[q]) - 1.f);
                if (EMIT == 1) {
                    __nv_bfloat16 h[4], l[4];
                    #pragma unroll
                    for (int q = 0; q < 4; q++) {
                        h[q] = __float2bfloat16(vv[q]);
                        l[q] = __float2bfloat16(vv[q] - __bfloat162float(h[q]));
                    }
                    __nv_bfloat16* r0p = Cp + (size_t)mbase*KP + col;
                    __nv_bfloat16* r1p = Cp + (size_t)(mbase+8)*KP + col;
                    *(__nv_bfloat162*)(r0p)      = __halves2bfloat162(h[0], h[1]);
                    *(__nv_bfloat162*)(r0p+512)  = __halves2bfloat162(h[0], h[1]);
                    *(__nv_bfloat162*)(r0p+1024) = __halves2bfloat162(l[0], l[1]);
                    *(__nv_bfloat162*)(r1p)      = __halves2bfloat162(h[2], h[3]);
                    *(__nv_bfloat162*)(r1p+512)  = __halves2bfloat162(h[2], h[3]);
                    *(__nv_bfloat162*)(r1p+1024) = __halves2bfloat162(l[2], l[3]);
                } else {  // EMIT == 2: tf32 lmhead activation
                    uint2 t0 = make_uint2(f2tf32(vv[0]), f2tf32(vv[1]));
                    uint2 t1 = make_uint2(f2tf32(vv[2]), f2tf32(vv[3]));
                    *(uint2*)(Ct + (size_t)mbase*DD + col)     = t0;
                    *(uint2*)(Ct + (size_t)(mbase+8)*DD + col) = t1;
                }
            }
        }
    }
}

// ---------------------------------------------------------------------------
// LM head v8: single-pass tf32. C = At @ Bt^T + bias (tf32, K=512).
// Same skeleton/addressing as the proven bf16 kernel: 128B rows now hold
// 32 tf32 per chunk; each former "k16 bf16 step" is a k8 tf32 step.
// CTA 128x256, 8 warps of 64x64, 3-stage cp.async.
// ---------------------------------------------------------------------------
#define L_STAGES 3
#define L_STAGE_BYTES 49152   // A 16KB + B 32KB
#define L_SMEM (L_STAGES*L_STAGE_BYTES)
#define L_OFF_B 16384u

__device__ __forceinline__ void load_stage_lm(
    const uint32_t* __restrict__ At, const uint32_t* __restrict__ Bt,
    int row0, int col0, int kk, uint32_t stage_base, int tid)
{
    #pragma unroll
    for (int it = 0; it < 12; it++) {
        int g = tid + it*256;              // 0..3071 granules of 16B
        bool isA = (g < 1024);             // A: 128 rows x 8 granules
        int gg  = isA ? g : (g - 1024);    // B: 256 rows x 8 granules
        int row = gg >> 3;
        int gran = gg & 7;                 // 16B = 4 tf32
        const uint32_t* src = (isA
            ? At + (size_t)(row0 + row)*DD
            : Bt + (size_t)(col0 + row)*DD) + kk + gran*4;
        uint32_t dst = stage_base + (isA ? 0u : L_OFF_B)
                     + (uint32_t)row*128u + (uint32_t)((gran ^ (row & 7)) << 4);
        cp_async16(dst, src);
    }
}

__global__ void __launch_bounds__(256, 1)
lmhead_k(const uint32_t* __restrict__ At,
         const uint32_t* __restrict__ Bt,
         const float* __restrict__ bias,
         float* __restrict__ C)
{
    extern __shared__ char smem[];
    const uint32_t sb = smem_u32(smem);
    const int tid  = threadIdx.x;
    const int wid  = tid >> 5;
    const int lane = tid & 31;
    const int row0 = blockIdx.x * 128;
    const int col0 = blockIdx.y * 256;

    const int warp_m = wid & 1;      // 2(m) x 4(n) warps; warp tile 64x64
    const int warp_n = wid >> 1;

    float acc[4][8][4];
    #pragma unroll
    for (int i = 0; i < 4; i++)
        #pragma unroll
        for (int j = 0; j < 8; j++)
            #pragma unroll
            for (int q = 0; q < 4; q++) acc[i][j][q] = 0.f;

    load_stage_lm(At, Bt, row0, col0, 0,  sb,                 tid); CP_COMMIT();
    load_stage_lm(At, Bt, row0, col0, 32, sb + L_STAGE_BYTES, tid); CP_COMMIT();

    const int a_row  = warp_m*64 + (lane & 15);
    const int a_gsel = lane >> 4;
    const int b_row  = warp_n*64 + ((lane >> 4) << 3) + (lane & 7);
    const int b_gsel = (lane >> 3) & 1;

    for (int c = 0; c < NCH_LM; c++) {
        cp_wait<L_STAGES-2>();
        __syncthreads();

        if (c + 2 < NCH_LM)
            load_stage_lm(At, Bt, row0, col0, (c+2)*32,
                          sb + ((c+2)%L_STAGES)*L_STAGE_BYTES, tid);
        CP_COMMIT();

        const uint32_t sA = sb + (c%L_STAGES)*L_STAGE_BYTES;
        const uint32_t sB = sA + L_OFF_B;

        #pragma unroll
        for (int s = 0; s < 4; s++) {   // four k8 (tf32) steps per 32-chunk
            uint32_t a[4][4];
            #pragma unroll
            for (int mi = 0; mi < 4; mi++) {
                int r = a_row + mi*16;
                int g = 2*s + a_gsel;
                uint32_t addr = sA + (uint32_t)r*128u + (uint32_t)((g ^ (r & 7)) << 4);
                ldmatrix_x4(a[mi][0], a[mi][1], a[mi][2], a[mi][3], addr);
            }
            uint32_t b[8][2];
            #pragma unroll
            for (int ng = 0; ng < 4; ng++) {
                int r = b_row + ng*16;
                int g = 2*s + b_gsel;
                uint32_t addr = sB + (uint32_t)r*128u + (uint32_t)((g ^ (r & 7)) << 4);
                uint32_t r0, r1, r2, r3;
                ldmatrix_x4(r0, r1, r2, r3, addr);
                b[ng*2+0][0] = r0; b[ng*2+0][1] = r1;
                b[ng*2+1][0] = r2; b[ng*2+1][1] = r3;
            }
            #pragma unroll
            for (int mi = 0; mi < 4; mi++)
                #pragma unroll
                for (int nj = 0; nj < 8; nj++)
                    mma_tf32(acc[mi][nj], a[mi][0], a[mi][1], a[mi][2], a[mi][3],
                             b[nj][0], b[nj][1]);
        }
    }

    const int trow = lane >> 2;
    const int tcol = (lane & 3) * 2;
    #pragma unroll
    for (int mi = 0; mi < 4; mi++) {
        const int mbase = row0 + warp_m*64 + mi*16 + trow;
        #pragma unroll
        for (int nj = 0; nj < 8; nj++) {
            const int col = col0 + warp_n*64 + nj*8 + tcol;
            const float b0 = __ldg(bias + col);
            const float b1 = __ldg(bias + col + 1);
            *(float2*)(C + (size_t)mbase*VV + col) =
                make_float2(acc[mi][nj][0] + b0, acc[mi][nj][1] + b1);
            *(float2*)(C + (size_t)(mbase+8)*VV + col) =
                make_float2(acc[mi][nj][2] + b0, acc[mi][nj][3] + b1);
        }
    }
}

// ---------------------------------------------------------------------------
// Host side
// ---------------------------------------------------------------------------
extern "C" void kernel_launch(void* const* d_in, const int* in_sizes, int n_in,
                              void* d_out, int out_size)
{
    const int*   ids = (const int*)  d_in[0];
    const float* emb = (const float*)d_in[1];
    const float* W1  = (const float*)d_in[2];
    const float* a1  = (const float*)d_in[3];
    const float* o1w = (const float*)d_in[4];
    const float* o1b = (const float*)d_in[5];
    const float* W2  = (const float*)d_in[6];
    const float* a2  = (const float*)d_in[7];
    const float* o2w = (const float*)d_in[8];
    const float* o2b = (const float*)d_in[9];
    const float* lmw = (const float*)d_in[10];
    const float* lmb = (const float*)d_in[11];
    float* out = (float*)d_out;

    float *pwx, *pssrc, *psdst;
    __nv_bfloat16 *pAp, *pAp2, *pWp;
    uint32_t *pAt, *pBt;
    cudaGetSymbolAddress((void**)&pwx,   g_wx);
    cudaGetSymbolAddress((void**)&pssrc, g_ssrc);
    cudaGetSymbolAddress((void**)&psdst, g_sdst);
    cudaGetSymbolAddress((void**)&pAp,   g_Ap);
    cudaGetSymbolAddress((void**)&pAp2,  g_Ap2);
    cudaGetSymbolAddress((void**)&pWp,   g_Wp);
    cudaGetSymbolAddress((void**)&pAt,   g_At);
    cudaGetSymbolAddress((void**)&pBt,   g_Bt);

    static bool attr_set = false;
    if (!attr_set) {
        cudaFuncSetAttribute(lmhead_k,     cudaFuncAttributeMaxDynamicSharedMemorySize, L_SMEM);
        cudaFuncSetAttribute(gat_mma_k<0>, cudaFuncAttributeMaxDynamicSharedMemorySize, G_SMEM);
        cudaFuncSetAttribute(gat_mma_k<1>, cudaFuncAttributeMaxDynamicSharedMemorySize, G_SMEM);
        cudaFuncSetAttribute(gat_mma_k<2>, cudaFuncAttributeMaxDynamicSharedMemorySize, G_SMEM);
        attr_set = true;
    }

    const dim3 gg(NN/128, DD/128);
    const int conv_w_blocks = (DD*(DD/4))/256;

    // LM-head weight conversion (fp32 -> tf32 bits)
    conv_tf32_k<<<(VV*(DD/4))/256, 256>>>(lmw, pBt);
    // Fused gather + GAT split (layer-1 GEMM1 input)
    gather_split_k<<<(NN*(DD/4))/256, 256>>>(ids, emb, pAp);

    // ---- Layer 1 ----
    conv_B_k<<<conv_w_blocks, 256>>>(W1, pWp);
    gat_mma_k<0><<<gg, 256, G_SMEM>>>(pAp, pWp, nullptr, pwx, nullptr, nullptr);
    scores_k<<<(NN*HH*32)/256, 256>>>(pwx, a1, pssrc, psdst);
    attn_split_k<<<NN, 128>>>(pwx, pssrc, psdst, pAp);
    conv_B_k<<<conv_w_blocks, 256>>>(o1w, pWp);
    gat_mma_k<1><<<gg, 256, G_SMEM>>>(pAp, pWp, o1b, nullptr, pAp2, nullptr);

    // ---- Layer 2 ----
    conv_B_k<<<conv_w_blocks, 256>>>(W2, pWp);
    gat_mma_k<0><<<gg, 256, G_SMEM>>>(pAp2, pWp, nullptr, pwx, nullptr, nullptr);
    scores_k<<<(NN*HH*32)/256, 256>>>(pwx, a2, pssrc, psdst);
    attn_split_k<<<NN, 128>>>(pwx, pssrc, psdst, pAp);
    conv_B_k<<<conv_w_blocks, 256>>>(o2w, pWp);
    gat_mma_k<2><<<gg, 256, G_SMEM>>>(pAp, pWp, o2b, nullptr, nullptr, pAt);

    // ---- LM head (grid.x = M blocks fast-varying -> B-tile L2 reuse) ----
    dim3 g(NN/128, VV/256);
    lmhead_k<<<g, 256, L_SMEM>>>(pAt, pBt, lmb, out);
}

// round 12
// speedup vs baseline: 1.6410x; 1.0339x over previous
#include <cuda_runtime.h>
#include <cuda_bf16.h>
#include <math.h>
#include <stdint.h>

// Problem constants (fixed by the reference)
#define BB 2
#define SS 2048
#define DD 512
#define VV 32000
#define HH 4
#define DH 128
#define WW 3
#define NN (BB*SS)   // 4096
#define NCH 16       // 512 / 32 tf32 per 128B row chunk

// Scratch (device globals; no allocation allowed)
__device__ float g_wx  [NN*DD];
__device__ float g_ssrc[NN*HH];
__device__ float g_sdst[NN*HH];
__device__ uint32_t g_t0 [(size_t)NN*DD];   // activations (tf32 bits)
__device__ uint32_t g_t1 [(size_t)NN*DD];   // attn output (tf32 bits)
__device__ uint32_t g_t2 [(size_t)NN*DD];   // layer hand-off (tf32 bits)
__device__ uint32_t g_Wt [(size_t)DD*DD];   // current weight (tf32 bits)
__device__ uint32_t g_Bt [(size_t)VV*DD];   // LM head weight (tf32 bits)

// ---------------------------------------------------------------------------
// PTX helpers (sm_80-era: cp.async, ldmatrix, mma.sync — valid at compute_103.
// tcgen05 is NOT available at the harness's virtual PTX target.)
// ---------------------------------------------------------------------------
__device__ __forceinline__ uint32_t smem_u32(const void* p) {
    uint32_t a;
    asm("{ .reg .u64 t; cvta.to.shared.u64 t, %1; cvt.u32.u64 %0, t; }"
        : "=r"(a) : "l"(p));
    return a;
}
__device__ __forceinline__ void cp_async16(uint32_t dst, const void* src) {
    asm volatile("cp.async.cg.shared.global [%0], [%1], 16;\n" :: "r"(dst), "l"(src));
}
#define CP_COMMIT() asm volatile("cp.async.commit_group;\n" ::: "memory")
template<int Nw> __device__ __forceinline__ void cp_wait() {
    asm volatile("cp.async.wait_group %0;\n" :: "n"(Nw) : "memory");
}
__device__ __forceinline__ void ldmatrix_x4(uint32_t& r0, uint32_t& r1,
                                            uint32_t& r2, uint32_t& r3, uint32_t addr) {
    asm volatile("ldmatrix.sync.aligned.m8n8.x4.shared.b16 {%0,%1,%2,%3}, [%4];\n"
                 : "=r"(r0), "=r"(r1), "=r"(r2), "=r"(r3) : "r"(addr));
}
// tf32 mma: fragments loaded with the SAME ldmatrix addressing as bf16 — each
// 32-bit register's two adjacent b16 slots reinterpret as one tf32 at half k.
__device__ __forceinline__ void mma_tf32(float* c,
                                         uint32_t a0, uint32_t a1, uint32_t a2, uint32_t a3,
                                         uint32_t b0, uint32_t b1) {
    asm volatile(
        "mma.sync.aligned.m16n8k8.row.col.f32.tf32.tf32.f32 "
        "{%0,%1,%2,%3}, {%4,%5,%6,%7}, {%8,%9}, {%0,%1,%2,%3};\n"
        : "+f"(c[0]), "+f"(c[1]), "+f"(c[2]), "+f"(c[3])
        : "r"(a0), "r"(a1), "r"(a2), "r"(a3), "r"(b0), "r"(b1));
}
__device__ __forceinline__ uint32_t f2tf32(float x) {
    uint32_t r;
    asm("cvt.rna.tf32.f32 %0, %1;" : "=r"(r) : "f"(x));
    return r;
}

// ---------------------------------------------------------------------------
// fp32 -> tf32 bits (generic, vectorized)
// ---------------------------------------------------------------------------
__global__ void conv_tf32_k(const float* __restrict__ src, uint32_t* __restrict__ dst)
{
    size_t i = (size_t)blockIdx.x * blockDim.x + threadIdx.x;
    size_t base = i * 4;
    float4 v = *(const float4*)(src + base);
    uint4 o;
    o.x = f2tf32(v.x); o.y = f2tf32(v.y); o.z = f2tf32(v.z); o.w = f2tf32(v.w);
    *(uint4*)(dst + base) = o;
}

// ---------------------------------------------------------------------------
// Fused embedding gather + tf32 convert
// ---------------------------------------------------------------------------
__global__ void gather_tf32_k(const int* __restrict__ ids,
                              const float* __restrict__ emb,
                              uint32_t* __restrict__ t0)
{
    int idx = blockIdx.x * blockDim.x + threadIdx.x;   // over NN*(DD/4)
    int n  = idx / (DD/4);
    int c  = (idx % (DD/4)) * 4;
    float4 v = *(const float4*)(emb + (size_t)ids[n]*DD + c);
    uint4 o;
    o.x = f2tf32(v.x); o.y = f2tf32(v.y); o.z = f2tf32(v.z); o.w = f2tf32(v.w);
    *(uint4*)(t0 + (size_t)n*DD + c) = o;
}

// ---------------------------------------------------------------------------
// Per-node attention scores
// ---------------------------------------------------------------------------
__global__ void scores_k(const float* __restrict__ wx,
                         const float* __restrict__ a,
                         float* __restrict__ ssrc,
                         float* __restrict__ sdst)
{
    int w    = (blockIdx.x * blockDim.x + threadIdx.x) >> 5;
    int lane = threadIdx.x & 31;
    if (w >= NN*HH) return;
    int n = w / HH, h = w % HH;
    const float* row = wx + (size_t)n*DD + h*DH;
    const float* au  = a + (size_t)h*2*DH;
    const float* av  = au + DH;

    int d = lane * 4;
    float4 x = *(const float4*)(row + d);
    float4 u = *(const float4*)(au  + d);
    float4 v = *(const float4*)(av  + d);
    float s1 = x.x*u.x + x.y*u.y + x.z*u.z + x.w*u.w;
    float s2 = x.x*v.x + x.y*v.y + x.z*v.z + x.w*v.w;
    #pragma unroll
    for (int o = 16; o; o >>= 1) {
        s1 += __shfl_xor_sync(0xffffffffu, s1, o);
        s2 += __shfl_xor_sync(0xffffffffu, s2, o);
    }
    if (lane == 0) { ssrc[w] = s1; sdst[w] = s2; }
}

// ---------------------------------------------------------------------------
// Windowed GAT aggregation, fused with tf32 convert
// ---------------------------------------------------------------------------
__global__ void attn_tf32_k(const float* __restrict__ wx,
                            const float* __restrict__ ssrc,
                            const float* __restrict__ sdst,
                            uint32_t* __restrict__ t1)
{
    int n    = blockIdx.x;
    int h    = threadIdx.x >> 5;
    int lane = threadIdx.x & 31;
    int i    = n % SS;

    float sd = sdst[(size_t)n*HH + h];

    float e[2*WW];
    int   jn[2*WW];
    int cnt = 0;
    #pragma unroll
    for (int off = -WW; off <= WW; off++) {
        if (off == 0) continue;
        int ji = i + off;
        if (ji < 0 || ji >= SS) continue;
        int j = n + off;
        float v = ssrc[(size_t)j*HH + h] + sd;
        v = v >= 0.f ? v : 0.2f * v;
        e[cnt] = v; jn[cnt] = j; cnt++;
    }
    float m = -1e30f;
    for (int c = 0; c < cnt; c++) m = fmaxf(m, e[c]);
    float den = 0.f;
    for (int c = 0; c < cnt; c++) { e[c] = expf(e[c] - m); den += e[c]; }
    float inv = 1.f / (den + 1e-16f);

    int d = lane * 4;
    float acc[4] = {0.f, 0.f, 0.f, 0.f};
    for (int c = 0; c < cnt; c++) {
        const float4 xv = *(const float4*)(wx + (size_t)jn[c]*DD + h*DH + d);
        float al = e[c] * inv;
        acc[0] = fmaf(al, xv.x, acc[0]);
        acc[1] = fmaf(al, xv.y, acc[1]);
        acc[2] = fmaf(al, xv.z, acc[2]);
        acc[3] = fmaf(al, xv.w, acc[3]);
    }
    uint4 o;
    o.x = f2tf32(acc[0]); o.y = f2tf32(acc[1]);
    o.z = f2tf32(acc[2]); o.w = f2tf32(acc[3]);
    *(uint4*)(t1 + (size_t)n*DD + h*DH + d) = o;
}

// ---------------------------------------------------------------------------
// Unified tf32 GEMM: C[M, Ncols] = At[M,512] @ Bt[Ncols,512]^T (+bias)(+epi)
// CTA 128xBN, 8 warps (2m x 4n), warp tile 64x(BN/4). BK=32 (128B rows),
// 3-stage cp.async. EMIT: 0 raw fp32 (stride DD); 1 bias+ELU -> tf32
// (stride DD); 2 bias -> fp32 (stride VV).
// ---------------------------------------------------------------------------
template<int BN> struct TFCfg {
    static constexpr int STAGE = (128 + BN) * 128;
    static constexpr int OFF_B = 16384;            // A: 128 rows * 128B
    static constexpr int NJ    = BN / 32;          // n8 frags per warp
    static constexpr int NG    = BN / 64;          // ldmatrix groups per warp
    static constexpr int WN    = BN / 4;           // warp tile N
    static constexpr int GRAN  = (128 + BN) * 8;   // 16B granules per stage
};

template<int BN, int EMIT>
__global__ void __launch_bounds__(256, (BN == 128 ? 2 : 1))
tf32_mma_k(const uint32_t* __restrict__ At,
           const uint32_t* __restrict__ Bt,
           const float* __restrict__ bias,
           float* __restrict__ Cf,
           uint32_t* __restrict__ Ct)
{
    using C = TFCfg<BN>;
    extern __shared__ char smem[];
    const uint32_t sb = smem_u32(smem);
    const int tid  = threadIdx.x;
    const int wid  = tid >> 5;
    const int lane = tid & 31;
    const int row0 = blockIdx.x * 128;
    const int col0 = blockIdx.y * BN;

    const int warp_m = wid & 1;
    const int warp_n = wid >> 1;

    float acc[4][C::NJ][4];
    #pragma unroll
    for (int i = 0; i < 4; i++)
        #pragma unroll
        for (int j = 0; j < C::NJ; j++)
            #pragma unroll
            for (int q = 0; q < 4; q++) acc[i][j][q] = 0.f;

    // stage loader (inlined lambda-style)
    auto load_stage = [&](int kk, uint32_t stage_base) {
        #pragma unroll
        for (int it = 0; it < C::GRAN/256; it++) {
            int g = tid + it*256;
            bool isA = (g < 1024);
            int gg  = isA ? g : (g - 1024);
            int row = gg >> 3;
            int gran = gg & 7;
            const uint32_t* src = (isA
                ? At + (size_t)(row0 + row)*DD
                : Bt + (size_t)(col0 + row)*DD) + kk + gran*4;
            uint32_t dst = stage_base + (isA ? 0u : (uint32_t)C::OFF_B)
                         + (uint32_t)row*128u + (uint32_t)((gran ^ (row & 7)) << 4);
            cp_async16(dst, src);
        }
    };

    load_stage(0,  sb);            CP_COMMIT();
    load_stage(32, sb + C::STAGE); CP_COMMIT();

    const int a_row  = warp_m*64 + (lane & 15);
    const int a_gsel = lane >> 4;
    const int b_row  = warp_n*C::WN + ((lane >> 4) << 3) + (lane & 7);
    const int b_gsel = (lane >> 3) & 1;

    for (int c = 0; c < NCH; c++) {
        cp_wait<1>();
        __syncthreads();

        if (c + 2 < NCH)
            load_stage((c+2)*32, sb + ((c+2)%3)*C::STAGE);
        CP_COMMIT();

        const uint32_t sA = sb + (c%3)*C::STAGE;
        const uint32_t sB = sA + C::OFF_B;

        #pragma unroll
        for (int s = 0; s < 4; s++) {   // four k8 (tf32) steps per 32-chunk
            uint32_t a[4][4];
            #pragma unroll
            for (int mi = 0; mi < 4; mi++) {
                int r = a_row + mi*16;
                int g = 2*s + a_gsel;
                uint32_t addr = sA + (uint32_t)r*128u + (uint32_t)((g ^ (r & 7)) << 4);
                ldmatrix_x4(a[mi][0], a[mi][1], a[mi][2], a[mi][3], addr);
            }
            uint32_t b[C::NJ][2];
            #pragma unroll
            for (int ng = 0; ng < C::NG; ng++) {
                int r = b_row + ng*16;
                int g = 2*s + b_gsel;
                uint32_t addr = sB + (uint32_t)r*128u + (uint32_t)((g ^ (r & 7)) << 4);
                uint32_t r0, r1, r2, r3;
                ldmatrix_x4(r0, r1, r2, r3, addr);
                b[ng*2+0][0] = r0; b[ng*2+0][1] = r1;
                b[ng*2+1][0] = r2; b[ng*2+1][1] = r3;
            }
            #pragma unroll
            for (int mi = 0; mi < 4; mi++)
                #pragma unroll
                for (int nj = 0; nj < C::NJ; nj++)
                    mma_tf32(acc[mi][nj], a[mi][0], a[mi][1], a[mi][2], a[mi][3],
                             b[nj][0], b[nj][1]);
        }
    }

    const int trow = lane >> 2;
    const int tcol = (lane & 3) * 2;
    const size_t cstride = (EMIT == 2) ? (size_t)VV : (size_t)DD;
    #pragma unroll
    for (int mi = 0; mi < 4; mi++) {
        const int mbase = row0 + warp_m*64 + mi*16 + trow;
        #pragma unroll
        for (int nj = 0; nj < C::NJ; nj++) {
            const int col = col0 + warp_n*C::WN + nj*8 + tcol;
            float v0 = acc[mi][nj][0], v1 = acc[mi][nj][1];
            float v2 = acc[mi][nj][2], v3 = acc[mi][nj][3];
            if (EMIT == 0) {
                *(float2*)(Cf + (size_t)mbase*cstride + col)     = make_float2(v0, v1);
                *(float2*)(Cf + (size_t)(mbase+8)*cstride + col) = make_float2(v2, v3);
            } else {
                const float b0 = __ldg(bias + col);
                const float b1 = __ldg(bias + col + 1);
                v0 += b0; v1 += b1; v2 += b0; v3 += b1;
                if (EMIT == 1) {
                    v0 = v0 > 0.f ? v0 : (expf(v0) - 1.f);
                    v1 = v1 > 0.f ? v1 : (expf(v1) - 1.f);
                    v2 = v2 > 0.f ? v2 : (expf(v2) - 1.f);
                    v3 = v3 > 0.f ? v3 : (expf(v3) - 1.f);
                    *(uint2*)(Ct + (size_t)mbase*cstride + col) =
                        make_uint2(f2tf32(v0), f2tf32(v1));
                    *(uint2*)(Ct + (size_t)(mbase+8)*cstride + col) =
                        make_uint2(f2tf32(v2), f2tf32(v3));
                } else {  // EMIT == 2
                    *(float2*)(Cf + (size_t)mbase*cstride + col)     = make_float2(v0, v1);
                    *(float2*)(Cf + (size_t)(mbase+8)*cstride + col) = make_float2(v2, v3);
                }
            }
        }
    }
}

// ---------------------------------------------------------------------------
// Host side
// ---------------------------------------------------------------------------
extern "C" void kernel_launch(void* const* d_in, const int* in_sizes, int n_in,
                              void* d_out, int out_size)
{
    const int*   ids = (const int*)  d_in[0];
    const float* emb = (const float*)d_in[1];
    const float* W1  = (const float*)d_in[2];
    const float* a1  = (const float*)d_in[3];
    const float* o1w = (const float*)d_in[4];
    const float* o1b = (const float*)d_in[5];
    const float* W2  = (const float*)d_in[6];
    const float* a2  = (const float*)d_in[7];
    const float* o2w = (const float*)d_in[8];
    const float* o2b = (const float*)d_in[9];
    const float* lmw = (const float*)d_in[10];
    const float* lmb = (const float*)d_in[11];
    float* out = (float*)d_out;

    float *pwx, *pssrc, *psdst;
    uint32_t *pt0, *pt1, *pt2, *pWt, *pBt;
    cudaGetSymbolAddress((void**)&pwx,   g_wx);
    cudaGetSymbolAddress((void**)&pssrc, g_ssrc);
    cudaGetSymbolAddress((void**)&psdst, g_sdst);
    cudaGetSymbolAddress((void**)&pt0,   g_t0);
    cudaGetSymbolAddress((void**)&pt1,   g_t1);
    cudaGetSymbolAddress((void**)&pt2,   g_t2);
    cudaGetSymbolAddress((void**)&pWt,   g_Wt);
    cudaGetSymbolAddress((void**)&pBt,   g_Bt);

    static bool attr_set = false;
    if (!attr_set) {
        cudaFuncSetAttribute((const void*)tf32_mma_k<128,0>,
            cudaFuncAttributeMaxDynamicSharedMemorySize, 3*TFCfg<128>::STAGE);
        cudaFuncSetAttribute((const void*)tf32_mma_k<128,1>,
            cudaFuncAttributeMaxDynamicSharedMemorySize, 3*TFCfg<128>::STAGE);
        cudaFuncSetAttribute((const void*)tf32_mma_k<256,2>,
            cudaFuncAttributeMaxDynamicSharedMemorySize, 3*TFCfg<256>::STAGE);
        attr_set = true;
    }

    const int GS = 3*TFCfg<128>::STAGE;   // 96 KB
    const int LS = 3*TFCfg<256>::STAGE;   // 144 KB
    const dim3 gg(NN/128, DD/128);
    const int conv_w_blocks = (DD*(DD/4))/256;

    // LM-head weight conversion (fp32 -> tf32 bits)
    conv_tf32_k<<<(VV*(DD/4))/256, 256>>>(lmw, pBt);
    // Fused gather + tf32 convert
    gather_tf32_k<<<(NN*(DD/4))/256, 256>>>(ids, emb, pt0);

    // ---- Layer 1 ----
    conv_tf32_k<<<conv_w_blocks, 256>>>(W1, pWt);
    tf32_mma_k<128,0><<<gg, 256, GS>>>(pt0, pWt, nullptr, pwx, nullptr);
    scores_k<<<(NN*HH*32)/256, 256>>>(pwx, a1, pssrc, psdst);
    attn_tf32_k<<<NN, 128>>>(pwx, pssrc, psdst, pt1);
    conv_tf32_k<<<conv_w_blocks, 256>>>(o1w, pWt);
    tf32_mma_k<128,1><<<gg, 256, GS>>>(pt1, pWt, o1b, nullptr, pt2);

    // ---- Layer 2 ----
    conv_tf32_k<<<conv_w_blocks, 256>>>(W2, pWt);
    tf32_mma_k<128,0><<<gg, 256, GS>>>(pt2, pWt, nullptr, pwx, nullptr);
    scores_k<<<(NN*HH*32)/256, 256>>>(pwx, a2, pssrc, psdst);
    attn_tf32_k<<<NN, 128>>>(pwx, pssrc, psdst, pt1);
    conv_tf32_k<<<conv_w_blocks, 256>>>(o2w, pWt);
    tf32_mma_k<128,1><<<gg, 256, GS>>>(pt1, pWt, o2b, nullptr, pt0);

    // ---- LM head (grid.x = M blocks fast-varying -> B-tile L2 reuse) ----
    dim3 g(NN/128, VV/256);
    tf32_mma_k<256,2><<<g, 256, LS>>>(pt0, pBt, lmb, out, nullptr);
}

// round 13
// speedup vs baseline: 1.6636x; 1.0138x over previous
#include <cuda_runtime.h>
#include <cuda_bf16.h>
#include <math.h>
#include <stdint.h>

// Problem constants (fixed by the reference)
#define BB 2
#define SS 2048
#define DD 512
#define VV 32000
#define HH 4
#define DH 128
#define WW 3
#define NN (BB*SS)   // 4096
#define NCH 16       // 512 / 32 tf32 per 128B row chunk

// Scratch (device globals; no allocation allowed)
__device__ float g_wx  [NN*DD];
__device__ float g_ssrc[NN*HH];
__device__ float g_sdst[NN*HH];
__device__ uint32_t g_t0 [(size_t)NN*DD];     // activations (tf32 bits)
__device__ uint32_t g_t1 [(size_t)NN*DD];     // attn output (tf32 bits)
__device__ uint32_t g_t2 [(size_t)NN*DD];     // layer hand-off (tf32 bits)
__device__ uint32_t g_Wt4[(size_t)4*DD*DD];   // all 4 GAT weights (tf32 bits)
__device__ uint32_t g_Bt [(size_t)VV*DD];     // LM head weight (tf32 bits)

// ---------------------------------------------------------------------------
// PTX helpers (sm_80-era: cp.async, ldmatrix, mma.sync — valid at compute_103.
// tcgen05 is NOT available at the harness's virtual PTX target.)
// ---------------------------------------------------------------------------
__device__ __forceinline__ uint32_t smem_u32(const void* p) {
    uint32_t a;
    asm("{ .reg .u64 t; cvta.to.shared.u64 t, %1; cvt.u32.u64 %0, t; }"
        : "=r"(a) : "l"(p));
    return a;
}
__device__ __forceinline__ void cp_async16(uint32_t dst, const void* src) {
    asm volatile("cp.async.cg.shared.global [%0], [%1], 16;\n" :: "r"(dst), "l"(src));
}
#define CP_COMMIT() asm volatile("cp.async.commit_group;\n" ::: "memory")
template<int Nw> __device__ __forceinline__ void cp_wait() {
    asm volatile("cp.async.wait_group %0;\n" :: "n"(Nw) : "memory");
}
__device__ __forceinline__ void ldmatrix_x4(uint32_t& r0, uint32_t& r1,
                                            uint32_t& r2, uint32_t& r3, uint32_t addr) {
    asm volatile("ldmatrix.sync.aligned.m8n8.x4.shared.b16 {%0,%1,%2,%3}, [%4];\n"
                 : "=r"(r0), "=r"(r1), "=r"(r2), "=r"(r3) : "r"(addr));
}
// tf32 mma: fragments loaded with the SAME ldmatrix addressing as bf16 — each
// 32-bit register's two adjacent b16 slots reinterpret as one tf32 at half k.
__device__ __forceinline__ void mma_tf32(float* c,
                                         uint32_t a0, uint32_t a1, uint32_t a2, uint32_t a3,
                                         uint32_t b0, uint32_t b1) {
    asm volatile(
        "mma.sync.aligned.m16n8k8.row.col.f32.tf32.tf32.f32 "
        "{%0,%1,%2,%3}, {%4,%5,%6,%7}, {%8,%9}, {%0,%1,%2,%3};\n"
        : "+f"(c[0]), "+f"(c[1]), "+f"(c[2]), "+f"(c[3])
        : "r"(a0), "r"(a1), "r"(a2), "r"(a3), "r"(b0), "r"(b1));
}
__device__ __forceinline__ uint32_t f2tf32(float x) {
    uint32_t r;
    asm("cvt.rna.tf32.f32 %0, %1;" : "=r"(r) : "f"(x));
    return r;
}

// ---------------------------------------------------------------------------
// fp32 -> tf32 bits (generic, vectorized)
// ---------------------------------------------------------------------------
__global__ void conv_tf32_k(const float* __restrict__ src, uint32_t* __restrict__ dst)
{
    size_t i = (size_t)blockIdx.x * blockDim.x + threadIdx.x;
    size_t base = i * 4;
    float4 v = *(const float4*)(src + base);
    uint4 o;
    o.x = f2tf32(v.x); o.y = f2tf32(v.y); o.z = f2tf32(v.z); o.w = f2tf32(v.w);
    *(uint4*)(dst + base) = o;
}

// All 4 GAT weights in one launch: dst blocks of DD*DD each
__global__ void conv_w4_k(const float* __restrict__ w0, const float* __restrict__ w1,
                          const float* __restrict__ w2, const float* __restrict__ w3,
                          uint32_t* __restrict__ dst)
{
    const int per = (DD*DD)/4;   // float4 groups per weight
    int i = blockIdx.x * blockDim.x + threadIdx.x;
    int which = i / per;
    int off   = i % per;
    const float* src = (which == 0) ? w0 : (which == 1) ? w1 : (which == 2) ? w2 : w3;
    float4 v = *(const float4*)(src + (size_t)off*4);
    uint4 o;
    o.x = f2tf32(v.x); o.y = f2tf32(v.y); o.z = f2tf32(v.z); o.w = f2tf32(v.w);
    *(uint4*)(dst + (size_t)which*DD*DD + (size_t)off*4) = o;
}

// ---------------------------------------------------------------------------
// Fused embedding gather + tf32 convert
// ---------------------------------------------------------------------------
__global__ void gather_tf32_k(const int* __restrict__ ids,
                              const float* __restrict__ emb,
                              uint32_t* __restrict__ t0)
{
    int idx = blockIdx.x * blockDim.x + threadIdx.x;   // over NN*(DD/4)
    int n  = idx / (DD/4);
    int c  = (idx % (DD/4)) * 4;
    float4 v = *(const float4*)(emb + (size_t)ids[n]*DD + c);
    uint4 o;
    o.x = f2tf32(v.x); o.y = f2tf32(v.y); o.z = f2tf32(v.z); o.w = f2tf32(v.w);
    *(uint4*)(t0 + (size_t)n*DD + c) = o;
}

// ---------------------------------------------------------------------------
// Windowed GAT aggregation, fused with tf32 convert
// ---------------------------------------------------------------------------
__global__ void attn_tf32_k(const float* __restrict__ wx,
                            const float* __restrict__ ssrc,
                            const float* __restrict__ sdst,
                            uint32_t* __restrict__ t1)
{
    int n    = blockIdx.x;
    int h    = threadIdx.x >> 5;
    int lane = threadIdx.x & 31;
    int i    = n % SS;

    float sd = sdst[(size_t)n*HH + h];

    float e[2*WW];
    int   jn[2*WW];
    int cnt = 0;
    #pragma unroll
    for (int off = -WW; off <= WW; off++) {
        if (off == 0) continue;
        int ji = i + off;
        if (ji < 0 || ji >= SS) continue;
        int j = n + off;
        float v = ssrc[(size_t)j*HH + h] + sd;
        v = v >= 0.f ? v : 0.2f * v;
        e[cnt] = v; jn[cnt] = j; cnt++;
    }
    float m = -1e30f;
    for (int c = 0; c < cnt; c++) m = fmaxf(m, e[c]);
    float den = 0.f;
    for (int c = 0; c < cnt; c++) { e[c] = expf(e[c] - m); den += e[c]; }
    float inv = 1.f / (den + 1e-16f);

    int d = lane * 4;
    float acc[4] = {0.f, 0.f, 0.f, 0.f};
    for (int c = 0; c < cnt; c++) {
        const float4 xv = *(const float4*)(wx + (size_t)jn[c]*DD + h*DH + d);
        float al = e[c] * inv;
        acc[0] = fmaf(al, xv.x, acc[0]);
        acc[1] = fmaf(al, xv.y, acc[1]);
        acc[2] = fmaf(al, xv.z, acc[2]);
        acc[3] = fmaf(al, xv.w, acc[3]);
    }
    uint4 o;
    o.x = f2tf32(acc[0]); o.y = f2tf32(acc[1]);
    o.z = f2tf32(acc[2]); o.w = f2tf32(acc[3]);
    *(uint4*)(t1 + (size_t)n*DD + h*DH + d) = o;
}

// ---------------------------------------------------------------------------
// Unified tf32 GEMM: C[M, Ncols] = At[M,512] @ Bt[Ncols,512]^T (+bias)(+epi)
// CTA 128xBN, 8 warps (2m x 4n), warp tile 64x(BN/4). BK=32 (128B rows),
// 3-stage cp.async.
// EMIT 0: raw fp32 -> Cf (stride DD) AND fused attention scores:
//         blockIdx.y == head h; ssrc/sdst written directly.
// EMIT 1: bias+ELU -> tf32 Ct (stride DD)
// EMIT 2: bias -> fp32 Cf (stride VV)
// ---------------------------------------------------------------------------
template<int BN> struct TFCfg {
    static constexpr int STAGE = (128 + BN) * 128;
    static constexpr int OFF_B = 16384;            // A: 128 rows * 128B
    static constexpr int NJ    = BN / 32;          // n8 frags per warp
    static constexpr int NG    = BN / 64;          // ldmatrix groups per warp
    static constexpr int WN    = BN / 4;           // warp tile N
    static constexpr int GRAN  = (128 + BN) * 8;   // 16B granules per stage
};

template<int BN, int EMIT>
__global__ void __launch_bounds__(256, (BN == 128 ? 2 : 1))
tf32_mma_k(const uint32_t* __restrict__ At,
           const uint32_t* __restrict__ Bt,
           const float* __restrict__ bias,
           float* __restrict__ Cf,
           uint32_t* __restrict__ Ct,
           const float* __restrict__ avec,   // EMIT 0: a[H][2*DH]
           float* __restrict__ ssrc,
           float* __restrict__ sdst)
{
    using C = TFCfg<BN>;
    extern __shared__ char smem[];
    const uint32_t sb = smem_u32(smem);
    const int tid  = threadIdx.x;
    const int wid  = tid >> 5;
    const int lane = tid & 31;
    const int row0 = blockIdx.x * 128;
    const int col0 = blockIdx.y * BN;

    const int warp_m = wid & 1;
    const int warp_n = wid >> 1;

    float acc[4][C::NJ][4];
    #pragma unroll
    for (int i = 0; i < 4; i++)
        #pragma unroll
        for (int j = 0; j < C::NJ; j++)
            #pragma unroll
            for (int q = 0; q < 4; q++) acc[i][j][q] = 0.f;

    auto load_stage = [&](int kk, uint32_t stage_base) {
        #pragma unroll
        for (int it = 0; it < C::GRAN/256; it++) {
            int g = tid + it*256;
            bool isA = (g < 1024);
            int gg  = isA ? g : (g - 1024);
            int row = gg >> 3;
            int gran = gg & 7;
            const uint32_t* src = (isA
                ? At + (size_t)(row0 + row)*DD
                : Bt + (size_t)(col0 + row)*DD) + kk + gran*4;
            uint32_t dst = stage_base + (isA ? 0u : (uint32_t)C::OFF_B)
                         + (uint32_t)row*128u + (uint32_t)((gran ^ (row & 7)) << 4);
            cp_async16(dst, src);
        }
    };

    load_stage(0,  sb);            CP_COMMIT();
    load_stage(32, sb + C::STAGE); CP_COMMIT();

    const int a_row  = warp_m*64 + (lane & 15);
    const int a_gsel = lane >> 4;
    const int b_row  = warp_n*C::WN + ((lane >> 4) << 3) + (lane & 7);
    const int b_gsel = (lane >> 3) & 1;

    for (int c = 0; c < NCH; c++) {
        cp_wait<1>();
        __syncthreads();

        if (c + 2 < NCH)
            load_stage((c+2)*32, sb + ((c+2)%3)*C::STAGE);
        CP_COMMIT();

        const uint32_t sA = sb + (c%3)*C::STAGE;
        const uint32_t sB = sA + C::OFF_B;

        #pragma unroll
        for (int s = 0; s < 4; s++) {   // four k8 (tf32) steps per 32-chunk
            uint32_t a[4][4];
            #pragma unroll
            for (int mi = 0; mi < 4; mi++) {
                int r = a_row + mi*16;
                int g = 2*s + a_gsel;
                uint32_t addr = sA + (uint32_t)r*128u + (uint32_t)((g ^ (r & 7)) << 4);
                ldmatrix_x4(a[mi][0], a[mi][1], a[mi][2], a[mi][3], addr);
            }
            uint32_t b[C::NJ][2];
            #pragma unroll
            for (int ng = 0; ng < C::NG; ng++) {
                int r = b_row + ng*16;
                int g = 2*s + b_gsel;
                uint32_t addr = sB + (uint32_t)r*128u + (uint32_t)((g ^ (r & 7)) << 4);
                uint32_t r0, r1, r2, r3;
                ldmatrix_x4(r0, r1, r2, r3, addr);
                b[ng*2+0][0] = r0; b[ng*2+0][1] = r1;
                b[ng*2+1][0] = r2; b[ng*2+1][1] = r3;
            }
            #pragma unroll
            for (int mi = 0; mi < 4; mi++)
                #pragma unroll
                for (int nj = 0; nj < C::NJ; nj++)
                    mma_tf32(acc[mi][nj], a[mi][0], a[mi][1], a[mi][2], a[mi][3],
                             b[nj][0], b[nj][1]);
        }
    }

    const int trow = lane >> 2;
    const int tcol = (lane & 3) * 2;
    const size_t cstride = (EMIT == 2) ? (size_t)VV : (size_t)DD;

    if (EMIT == 0) {
        // ---- write wx + fused per-head attention scores ----
        const int h = blockIdx.y;   // BN==128: one head per column block
        const float* as = avec + (size_t)h*2*DH;
        const float* ad = as + DH;
        float psrc[4][2], pdst[4][2];
        #pragma unroll
        for (int mi = 0; mi < 4; mi++) {
            psrc[mi][0] = psrc[mi][1] = 0.f;
            pdst[mi][0] = pdst[mi][1] = 0.f;
        }
        #pragma unroll
        for (int mi = 0; mi < 4; mi++) {
            const int mbase = row0 + warp_m*64 + mi*16 + trow;
            #pragma unroll
            for (int nj = 0; nj < C::NJ; nj++) {
                const int jl  = warp_n*C::WN + nj*8 + tcol;   // local col 0..127
                const int col = col0 + jl;
                float v0 = acc[mi][nj][0], v1 = acc[mi][nj][1];
                float v2 = acc[mi][nj][2], v3 = acc[mi][nj][3];
                *(float2*)(Cf + (size_t)mbase*DD + col)     = make_float2(v0, v1);
                *(float2*)(Cf + (size_t)(mbase+8)*DD + col) = make_float2(v2, v3);
                const float s0 = __ldg(as + jl), s1 = __ldg(as + jl + 1);
                const float d0 = __ldg(ad + jl), d1 = __ldg(ad + jl + 1);
                psrc[mi][0] = fmaf(v0, s0, fmaf(v1, s1, psrc[mi][0]));
                psrc[mi][1] = fmaf(v2, s0, fmaf(v3, s1, psrc[mi][1]));
                pdst[mi][0] = fmaf(v0, d0, fmaf(v1, d1, pdst[mi][0]));
                pdst[mi][1] = fmaf(v2, d0, fmaf(v3, d1, pdst[mi][1]));
            }
        }
        // butterfly over the 4-lane col group -> every lane holds group sum
        #pragma unroll
        for (int off = 1; off <= 2; off <<= 1)
            #pragma unroll
            for (int mi = 0; mi < 4; mi++)
                #pragma unroll
                for (int p = 0; p < 2; p++) {
                    psrc[mi][p] += __shfl_xor_sync(0xffffffffu, psrc[mi][p], off);
                    pdst[mi][p] += __shfl_xor_sync(0xffffffffu, pdst[mi][p], off);
                }
        __syncthreads();                 // all warps done reading stage smem
        float* red = (float*)smem;       // [2][4 warp_n][128 row] = 4KB
        if ((lane & 3) == 0) {
            #pragma unroll
            for (int mi = 0; mi < 4; mi++)
                #pragma unroll
                for (int p = 0; p < 2; p++) {
                    int rl = warp_m*64 + mi*16 + trow + p*8;
                    red[0*512 + warp_n*128 + rl] = psrc[mi][p];
                    red[1*512 + warp_n*128 + rl] = pdst[mi][p];
                }
        }
        __syncthreads();
        {
            int sd = tid >> 7;           // 0: src, 1: dst
            int rl = tid & 127;
            float s = red[sd*512 + 0*128 + rl] + red[sd*512 + 1*128 + rl]
                    + red[sd*512 + 2*128 + rl] + red[sd*512 + 3*128 + rl];
            float* outp = sd ? sdst : ssrc;
            outp[(size_t)(row0 + rl)*HH + h] = s;
        }
        return;
    }

    #pragma unroll
    for (int mi = 0; mi < 4; mi++) {
        const int mbase = row0 + warp_m*64 + mi*16 + trow;
        #pragma unroll
        for (int nj = 0; nj < C::NJ; nj++) {
            const int col = col0 + warp_n*C::WN + nj*8 + tcol;
            float v0 = acc[mi][nj][0], v1 = acc[mi][nj][1];
            float v2 = acc[mi][nj][2], v3 = acc[mi][nj][3];
            const float b0 = __ldg(bias + col);
            const float b1 = __ldg(bias + col + 1);
            v0 += b0; v1 += b1; v2 += b0; v3 += b1;
            if (EMIT == 1) {
                v0 = v0 > 0.f ? v0 : (expf(v0) - 1.f);
                v1 = v1 > 0.f ? v1 : (expf(v1) - 1.f);
                v2 = v2 > 0.f ? v2 : (expf(v2) - 1.f);
                v3 = v3 > 0.f ? v3 : (expf(v3) - 1.f);
                *(uint2*)(Ct + (size_t)mbase*cstride + col) =
                    make_uint2(f2tf32(v0), f2tf32(v1));
                *(uint2*)(Ct + (size_t)(mbase+8)*cstride + col) =
                    make_uint2(f2tf32(v2), f2tf32(v3));
            } else {  // EMIT == 2
                *(float2*)(Cf + (size_t)mbase*cstride + col)     = make_float2(v0, v1);
                *(float2*)(Cf + (size_t)(mbase+8)*cstride + col) = make_float2(v2, v3);
            }
        }
    }
}

// ---------------------------------------------------------------------------
// Host side
// ---------------------------------------------------------------------------
extern "C" void kernel_launch(void* const* d_in, const int* in_sizes, int n_in,
                              void* d_out, int out_size)
{
    const int*   ids = (const int*)  d_in[0];
    const float* emb = (const float*)d_in[1];
    const float* W1  = (const float*)d_in[2];
    const float* a1  = (const float*)d_in[3];
    const float* o1w = (const float*)d_in[4];
    const float* o1b = (const float*)d_in[5];
    const float* W2  = (const float*)d_in[6];
    const float* a2  = (const float*)d_in[7];
    const float* o2w = (const float*)d_in[8];
    const float* o2b = (const float*)d_in[9];
    const float* lmw = (const float*)d_in[10];
    const float* lmb = (const float*)d_in[11];
    float* out = (float*)d_out;

    float *pwx, *pssrc, *psdst;
    uint32_t *pt0, *pt1, *pt2, *pWt4, *pBt;
    cudaGetSymbolAddress((void**)&pwx,   g_wx);
    cudaGetSymbolAddress((void**)&pssrc, g_ssrc);
    cudaGetSymbolAddress((void**)&psdst, g_sdst);
    cudaGetSymbolAddress((void**)&pt0,   g_t0);
    cudaGetSymbolAddress((void**)&pt1,   g_t1);
    cudaGetSymbolAddress((void**)&pt2,   g_t2);
    cudaGetSymbolAddress((void**)&pWt4,  g_Wt4);
    cudaGetSymbolAddress((void**)&pBt,   g_Bt);

    static bool attr_set = false;
    if (!attr_set) {
        cudaFuncSetAttribute((const void*)tf32_mma_k<128,0>,
            cudaFuncAttributeMaxDynamicSharedMemorySize, 3*TFCfg<128>::STAGE);
        cudaFuncSetAttribute((const void*)tf32_mma_k<128,1>,
            cudaFuncAttributeMaxDynamicSharedMemorySize, 3*TFCfg<128>::STAGE);
        cudaFuncSetAttribute((const void*)tf32_mma_k<256,2>,
            cudaFuncAttributeMaxDynamicSharedMemorySize, 3*TFCfg<256>::STAGE);
        attr_set = true;
    }

    const int GS = 3*TFCfg<128>::STAGE;   // 96 KB
    const int LS = 3*TFCfg<256>::STAGE;   // 144 KB
    const dim3 gg(NN/128, DD/128);

    // Independent prep: lmhead weights, all 4 GAT weights, gather
    conv_tf32_k<<<(VV*(DD/4))/256, 256>>>(lmw, pBt);
    conv_w4_k<<<(4*(DD*DD/4))/256, 256>>>(W1, o1w, W2, o2w, pWt4);
    gather_tf32_k<<<(NN*(DD/4))/256, 256>>>(ids, emb, pt0);

    uint32_t* pW1  = pWt4;
    uint32_t* pO1  = pWt4 + (size_t)1*DD*DD;
    uint32_t* pW2  = pWt4 + (size_t)2*DD*DD;
    uint32_t* pO2  = pWt4 + (size_t)3*DD*DD;

    // ---- Layer 1 ----
    tf32_mma_k<128,0><<<gg, 256, GS>>>(pt0, pW1, nullptr, pwx, nullptr, a1, pssrc, psdst);
    attn_tf32_k<<<NN, 128>>>(pwx, pssrc, psdst, pt1);
    tf32_mma_k<128,1><<<gg, 256, GS>>>(pt1, pO1, o1b, nullptr, pt2, nullptr, nullptr, nullptr);

    // ---- Layer 2 ----
    tf32_mma_k<128,0><<<gg, 256, GS>>>(pt2, pW2, nullptr, pwx, nullptr, a2, pssrc, psdst);
    attn_tf32_k<<<NN, 128>>>(pwx, pssrc, psdst, pt1);
    tf32_mma_k<128,1><<<gg, 256, GS>>>(pt1, pO2, o2b, nullptr, pt0, nullptr, nullptr, nullptr);

    // ---- LM head (grid.x = M blocks fast-varying -> B-tile L2 reuse) ----
    dim3 g(NN/128, VV/256);
    tf32_mma_k<256,2><<<g, 256, LS>>>(pt0, pBt, lmb, out, nullptr, nullptr, nullptr, nullptr);
}